// round 8
// baseline (speedup 1.0000x reference)
#include <cuda_runtime.h>

#define BB 16
#define LL 24
#define NN 256
#define EE 4096
#define TT (BB*LL)      // 384 graphs
#define BN (BB*NN)      // 4096 LSTM samples
#define S_MAX 14        // samples per LSTM block (293 blocks, 2 blocks/SM)
#define PN 268          // padded node stride for transposed X

// ---------------- packed f32x2 helpers ----------------
__device__ __forceinline__ unsigned long long packf2(float lo, float hi) {
    unsigned long long r;
    asm("mov.b64 %0,{%1,%2};" : "=l"(r) : "f"(lo), "f"(hi));
    return r;
}
__device__ __forceinline__ void unpackf2(unsigned long long v, float& lo, float& hi) {
    asm("mov.b64 {%0,%1},%2;" : "=f"(lo), "=f"(hi) : "l"(v));
}
__device__ __forceinline__ void ffma2(unsigned long long& d, unsigned long long a,
                                      unsigned long long b) {
    asm("fma.rn.f32x2 %0,%1,%2,%0;" : "+l"(d) : "l"(a), "l"(b));
}
__device__ __forceinline__ float tanha(float x) {
    float r; asm("tanh.approx.f32 %0,%1;" : "=f"(r) : "f"(x)); return r;
}
__device__ __forceinline__ float fsig(float x) { return 0.5f * tanha(0.5f * x) + 0.5f; }

// ---------------- device scratch ----------------
__device__ float g_Hout[TT * NN * 64];     // 25 MB
__device__ float g_M1[4096];
__device__ float g_M2[4096];
__device__ float g_Wc[4096];
__device__ float g_G0[64], g_G1[64], g_Gb[64];
__device__ float g_s0v[NN], g_s1v[NN];
__device__ int   g_deg[NN];
__device__ int   g_off[NN + 1];
__device__ int   g_src[EE];

// ---------------- merged setup: block 0 = CSR/graph, blocks 1..65 = weight folds ----
__global__ void setup_all(const int* __restrict__ conn,
                          const float* __restrict__ city_w,
                          const float* __restrict__ W1,   // [130,64]
                          const float* __restrict__ b1,   // [64]
                          const float* __restrict__ W2)   // [128,64]
{
    int t = threadIdx.x;
    if (blockIdx.x == 0) {
        __shared__ float s0[NN], s1[NN];
        __shared__ int degs[NN], cur[NN], scan[NN];

        if (t < NN) { s0[t] = 0.f; s1[t] = 0.f; degs[t] = 0; }
        __syncthreads();

        const int* row = conn;
        const int* col = conn + EE;
#pragma unroll
        for (int u = 0; u < EE / 1024; u++) {
            int e = u * 1024 + t;
            int c = col[e];
            atomicAdd(&degs[c], 1);
            atomicAdd(&s0[c], city_w[2 * e + 0]);
            atomicAdd(&s1[c], city_w[2 * e + 1]);
        }
        __syncthreads();

        if (t < NN) scan[t] = degs[t];
        __syncthreads();
        for (int d = 1; d < NN; d <<= 1) {
            int v = (t < NN && t >= d) ? scan[t - d] : 0;
            __syncthreads();
            if (t < NN) scan[t] += v;
            __syncthreads();
        }
        if (t < NN) {
            int excl = scan[t] - degs[t];
            g_off[t] = excl;
            cur[t] = excl;
            g_deg[t] = degs[t];
            g_s0v[t] = s0[t];
            g_s1v[t] = s1[t];
            if (t == NN - 1) g_off[NN] = scan[NN - 1];
        }
        __syncthreads();
#pragma unroll
        for (int u = 0; u < EE / 1024; u++) {
            int e = u * 1024 + t;
            int c = col[e];
            int p = atomicAdd(&cur[c], 1);
            g_src[p] = row[e];
        }
    } else {
        int k = blockIdx.x - 1;
        int c = t;
        const float* W2b = W2 + 4096;
        if (k < 64) {
            __shared__ float w1a[64], w1b[64];
            if (c < 64) { w1a[c] = W1[k * 64 + c]; w1b[c] = W1[4096 + k * 64 + c]; }
            __syncthreads();
            if (c < 64) {
                float p0 = 0.f, p1 = 0.f, p2 = 0.f, p3 = 0.f;
                float q0 = 0.f, q1 = 0.f, q2 = 0.f, q3 = 0.f;
#pragma unroll
                for (int j = 0; j < 64; j += 4) {
                    float v0 = W2b[(j + 0) * 64 + c];
                    float v1 = W2b[(j + 1) * 64 + c];
                    float v2 = W2b[(j + 2) * 64 + c];
                    float v3 = W2b[(j + 3) * 64 + c];
                    p0 += w1a[j + 0] * v0; q0 += w1b[j + 0] * v0;
                    p1 += w1a[j + 1] * v1; q1 += w1b[j + 1] * v1;
                    p2 += w1a[j + 2] * v2; q2 += w1b[j + 2] * v2;
                    p3 += w1a[j + 3] * v3; q3 += w1b[j + 3] * v3;
                }
                float a1 = (p0 + p1) + (p2 + p3);
                float a2 = (q0 + q1) + (q2 + q3);
                g_M1[k * 64 + c] = a1;
                g_M2[k * 64 + c] = a2;
                g_Wc[k * 64 + c] = W2[k * 64 + c] + a2;
            }
        } else if (c < 64) {
            float a0 = 0.f, a1 = 0.f, ab = 0.f;
#pragma unroll 8
            for (int j = 0; j < 64; j++) {
                float w2 = W2b[j * 64 + c];
                a0 += W1[128 * 64 + j] * w2;
                a1 += W1[129 * 64 + j] * w2;
                ab += b1[j] * w2;
            }
            g_G0[c] = a0; g_G1[c] = a1; g_Gb[c] = ab;
        }
    }
}

// ---------------- LSTM: 512 threads, split-K lane pairs, 2 blocks/SM ----------------
__global__ void __launch_bounds__(512, 2)
lstm_kernel(const float* __restrict__ aqi,
            const float* __restrict__ embW,
            const float* __restrict__ embB,
            const float* __restrict__ Wih,
            const float* __restrict__ Whh,
            const float* __restrict__ bih,
            const float* __restrict__ bhh)
{
    __shared__ __align__(16) float hS[S_MAX][64];
    __shared__ __align__(16) float cS[S_MAX][64];
    __shared__ __align__(16) float gS[S_MAX][256];
    __shared__ float aS[S_MAX][LL];

    int tid = threadIdx.x;
    int m0  = blockIdx.x * S_MAX;
    int cnt = BN - m0; if (cnt > S_MAX) cnt = S_MAX;

    int r  = tid >> 1;      // gate row 0..255
    int kh = tid & 1;       // k-half 0/1

    // half weight row: Whh[r][32*kh .. 32*kh+31] as 16 f32x2
    unsigned long long w2[16];
    {
        const ulonglong2* wr = (const ulonglong2*)(Whh + r * 64 + kh * 32);
#pragma unroll
        for (int i = 0; i < 8; i++) {
            ulonglong2 v = wr[i];
            w2[2 * i] = v.x; w2[2 * i + 1] = v.y;
        }
    }
    float A = 0.f, Bc = 0.f;
#pragma unroll
    for (int j = 0; j < 16; j++) {
        float wi = Wih[r * 16 + j];
        A  += wi * embW[j];
        Bc += wi * embB[j];
    }
    Bc += bih[r] + bhh[r];

    for (int idx = tid; idx < cnt * LL; idx += 512) {
        int s = idx / LL, l = idx % LL;
        int m = m0 + s; int b = m >> 8; int n = m & 255;
        aS[s][l] = aqi[(b * LL + l) * NN + n];
    }
    for (int idx = tid; idx < cnt * 64; idx += 512) {
        ((float*)hS)[idx] = 0.f; ((float*)cS)[idx] = 0.f;
    }
    __syncthreads();

    // epilogue mapping: warp = one sample, lane = 2 channels
    int se = tid >> 5;            // 0..15
    int jj = (tid & 31) * 2;      // 0..62
    int me = m0 + se; int be = me >> 8; int ne = me & 255;
    float* hout_base = g_Hout + ((size_t)(be * LL) * NN + ne) * 64 + jj;

    for (int l = 0; l < LL; l++) {
#pragma unroll 2
        for (int s = 0; s < cnt; s++) {
            unsigned long long a0 = 0ull, a1 = 0ull;
            const ulonglong2* hp = (const ulonglong2*)(hS[s] + kh * 32);
#pragma unroll
            for (int i = 0; i < 8; i++) {
                ulonglong2 h = hp[i];
                ffma2(a0, h.x, w2[2 * i]);
                ffma2(a1, h.y, w2[2 * i + 1]);
            }
            float l0, h0, l1, h1;
            unpackf2(a0, l0, h0); unpackf2(a1, l1, h1);
            float part = (l0 + h0) + (l1 + h1);
            part += __shfl_xor_sync(0xffffffffu, part, 1);
            if (kh == 0)
                gS[s][r] = aS[s][l] * A + Bc + part;
        }
        __syncthreads();
        if (se < cnt) {
            float2 gi = *(const float2*)&gS[se][jj];
            float2 gf = *(const float2*)&gS[se][64 + jj];
            float2 gg = *(const float2*)&gS[se][128 + jj];
            float2 go = *(const float2*)&gS[se][192 + jj];
            float2 c2 = *(const float2*)&cS[se][jj];
            c2.x = fsig(gf.x) * c2.x + fsig(gi.x) * tanha(gg.x);
            c2.y = fsig(gf.y) * c2.y + fsig(gi.y) * tanha(gg.y);
            float2 h2;
            h2.x = fsig(go.x) * tanha(c2.x);
            h2.y = fsig(go.y) * tanha(c2.y);
            *(float2*)&cS[se][jj] = c2;
            *(float2*)&hS[se][jj] = h2;
            *(float2*)(hout_base + (size_t)l * NN * 64) = h2;
        }
        __syncthreads();
    }
}

// ---------------- fused GNN: 128 blocks x 3 graphs, 512 threads ----------------
#define FUSE_SMEM_FLOATS (64 * PN + 16384 + 4096 + 4096 + 64 + 192 + 512 + 4096 + 257 + 256)
#define FUSE_SMEM_BYTES  (FUSE_SMEM_FLOATS * 4)

__global__ void __launch_bounds__(512, 1)
gnn_fused(const float* __restrict__ b2, float* __restrict__ out)
{
    extern __shared__ __align__(16) float sm[];
    float* Xk  = sm;                       // 64*PN (transposed X; aliased as Zbuf later)
    float* Vs  = Xk + 64 * PN;             // 256*64
    float* W1s = Vs + 16384;               // 4096
    float* Wcs = W1s + 4096;               // 4096
    float* b2s = Wcs + 4096;               // 64
    float* G0s = b2s + 64;                 // 64
    float* G1s = G0s + 64;                 // 64
    float* Gbs = G1s + 64;                 // 64
    float* s0S = Gbs + 64;                 // 256
    float* s1S = s0S + 256;                // 256
    int* srcS  = (int*)(s1S + 256);        // 4096
    int* offS  = srcS + EE;                // 257
    int* degS  = offS + NN + 1;            // 256

    int tid = threadIdx.x;
    for (int i = tid; i < 4096; i += 512) {
        W1s[i] = g_M1[i];
        Wcs[i] = g_Wc[i];
        srcS[i] = g_src[i];
    }
    if (tid < 64) {
        b2s[tid] = b2[tid];
        G0s[tid] = g_G0[tid]; G1s[tid] = g_G1[tid]; Gbs[tid] = g_Gb[tid];
    }
    if (tid < 256) { s0S[tid] = g_s0v[tid]; s1S[tid] = g_s1v[tid]; degS[tid] = g_deg[tid]; }
    if (tid < 257) offS[tid] = g_off[tid];

    int cg = tid & 15, ng = tid >> 4;
    int c0 = cg * 4, n0 = ng * 8;
    int lane = tid & 31, warp = tid >> 5;

    for (int g = 0; g < 3; g++) {
        int t = blockIdx.x * 3 + g;
        const float* Xg = g_Hout + (size_t)t * NN * 64;
        for (int idx = tid; idx < NN * 64; idx += 512) {
            int n = idx >> 6, c = idx & 63;
            Xk[c * PN + n] = Xg[idx];
        }
        __syncthreads();   // X ready

        unsigned long long acc1[16], acc2[16];
#pragma unroll
        for (int i = 0; i < 16; i++) { acc1[i] = 0ull; acc2[i] = 0ull; }

        // ---- fused mm1 (V = X@M1) + mm2 (Z = X@Wc) : X read once ----
#pragma unroll 4
        for (int k = 0; k < 64; k++) {
            float4 xa = *(const float4*)(Xk + k * PN + n0);
            float4 xb = *(const float4*)(Xk + k * PN + n0 + 4);
            ulonglong2 w1 = *(const ulonglong2*)(W1s + k * 64 + c0);
            ulonglong2 wc = *(const ulonglong2*)(Wcs + k * 64 + c0);
            unsigned long long x;
            x = packf2(xa.x, xa.x);
            ffma2(acc1[0],  x, w1.x); ffma2(acc1[1],  x, w1.y);
            ffma2(acc2[0],  x, wc.x); ffma2(acc2[1],  x, wc.y);
            x = packf2(xa.y, xa.y);
            ffma2(acc1[2],  x, w1.x); ffma2(acc1[3],  x, w1.y);
            ffma2(acc2[2],  x, wc.x); ffma2(acc2[3],  x, wc.y);
            x = packf2(xa.z, xa.z);
            ffma2(acc1[4],  x, w1.x); ffma2(acc1[5],  x, w1.y);
            ffma2(acc2[4],  x, wc.x); ffma2(acc2[5],  x, wc.y);
            x = packf2(xa.w, xa.w);
            ffma2(acc1[6],  x, w1.x); ffma2(acc1[7],  x, w1.y);
            ffma2(acc2[6],  x, wc.x); ffma2(acc2[7],  x, wc.y);
            x = packf2(xb.x, xb.x);
            ffma2(acc1[8],  x, w1.x); ffma2(acc1[9],  x, w1.y);
            ffma2(acc2[8],  x, wc.x); ffma2(acc2[9],  x, wc.y);
            x = packf2(xb.y, xb.y);
            ffma2(acc1[10], x, w1.x); ffma2(acc1[11], x, w1.y);
            ffma2(acc2[10], x, wc.x); ffma2(acc2[11], x, wc.y);
            x = packf2(xb.z, xb.z);
            ffma2(acc1[12], x, w1.x); ffma2(acc1[13], x, w1.y);
            ffma2(acc2[12], x, wc.x); ffma2(acc2[13], x, wc.y);
            x = packf2(xb.w, xb.w);
            ffma2(acc1[14], x, w1.x); ffma2(acc1[15], x, w1.y);
            ffma2(acc2[14], x, wc.x); ffma2(acc2[15], x, wc.y);
        }

        // V -> Vs
#pragma unroll
        for (int n = 0; n < 8; n++) {
            float4 v;
            unpackf2(acc1[2 * n], v.x, v.y);
            unpackf2(acc1[2 * n + 1], v.z, v.w);
            *(float4*)(Vs + (n0 + n) * 64 + c0) = v;
        }

        // Z = acc2 + b2 (deg==0 rare path: subtract X@M2)
        float4 bb = *(const float4*)(b2s + c0);
        float4 z[8];
#pragma unroll
        for (int n = 0; n < 8; n++) {
            unpackf2(acc2[2 * n], z[n].x, z[n].y);
            unpackf2(acc2[2 * n + 1], z[n].z, z[n].w);
            z[n].x += bb.x; z[n].y += bb.y; z[n].z += bb.z; z[n].w += bb.w;
            if (degS[n0 + n] == 0) {
                float s0c = 0.f, s1c = 0.f, s2c = 0.f, s3c = 0.f;
                for (int k = 0; k < 64; k++) {
                    float xv = Xk[k * PN + n0 + n];
                    s0c += xv * g_M2[k * 64 + c0 + 0];
                    s1c += xv * g_M2[k * 64 + c0 + 1];
                    s2c += xv * g_M2[k * 64 + c0 + 2];
                    s3c += xv * g_M2[k * 64 + c0 + 3];
                }
                z[n].x -= s0c; z[n].y -= s1c; z[n].z -= s2c; z[n].w -= s3c;
            }
        }
        __syncthreads();   // all Xk reads done; Vs complete

        float* Zb = Xk;    // reuse X space for Z (node-major, stride 64)
#pragma unroll
        for (int n = 0; n < 8; n++)
            *(float4*)(Zb + (n0 + n) * 64 + c0) = z[n];
        __syncthreads();   // Zb ready

        // ---- gather: out = Z + (sum_in V + Cp)/deg ----
        for (int n = warp; n < NN; n += 16) {
            int lo = offS[n], hi = offS[n + 1];
            float a0 = 0.f, a1 = 0.f;
            int e = lo;
            for (; e + 4 <= hi; e += 4) {
                int i0 = srcS[e], i1 = srcS[e + 1], i2 = srcS[e + 2], i3 = srcS[e + 3];
                a0 += Vs[i0 * 64 + lane]      + Vs[i1 * 64 + lane]
                    + Vs[i2 * 64 + lane]      + Vs[i3 * 64 + lane];
                a1 += Vs[i0 * 64 + 32 + lane] + Vs[i1 * 64 + 32 + lane]
                    + Vs[i2 * 64 + 32 + lane] + Vs[i3 * 64 + 32 + lane];
            }
            for (; e < hi; e++) {
                int i0 = srcS[e];
                a0 += Vs[i0 * 64 + lane];
                a1 += Vs[i0 * 64 + 32 + lane];
            }
            float degf = (float)(hi - lo);
            float dinv = 1.f / fmaxf(degf, 1.f);
            float sn0 = s0S[n], sn1 = s1S[n];
            float cp0 = sn0 * G0s[lane]      + sn1 * G1s[lane]      + degf * Gbs[lane];
            float cp1 = sn0 * G0s[32 + lane] + sn1 * G1s[32 + lane] + degf * Gbs[32 + lane];
            float* op = out + ((size_t)t * NN + n) * 64;
            op[lane]      = Zb[n * 64 + lane]      + (a0 + cp0) * dinv;
            op[32 + lane] = Zb[n * 64 + 32 + lane] + (a1 + cp1) * dinv;
        }
        __syncthreads();   // protect Xk/Vs before next graph
    }
}

// ---------------- launch ----------------
extern "C" void kernel_launch(void* const* d_in, const int* in_sizes, int n_in,
                              void* d_out, int out_size)
{
    const float* aqi  = (const float*)d_in[0];
    const int*   conn = (const int*)  d_in[1];
    const float* cw   = (const float*)d_in[2];
    const float* embW = (const float*)d_in[3];
    const float* embB = (const float*)d_in[4];
    const float* Wih  = (const float*)d_in[5];
    const float* Whh  = (const float*)d_in[6];
    const float* bih  = (const float*)d_in[7];
    const float* bhh  = (const float*)d_in[8];
    const float* W1   = (const float*)d_in[9];
    const float* b1   = (const float*)d_in[10];
    const float* W2   = (const float*)d_in[11];
    const float* b2   = (const float*)d_in[12];
    float* out = (float*)d_out;

    int lstm_blocks = (BN + S_MAX - 1) / S_MAX;   // 293
    lstm_kernel<<<lstm_blocks, 512>>>(aqi, embW, embB, Wih, Whh, bih, bhh);
    setup_all<<<66, 1024>>>(conn, cw, W1, b1, W2);
    cudaFuncSetAttribute(gnn_fused, cudaFuncAttributeMaxDynamicSharedMemorySize,
                         FUSE_SMEM_BYTES);
    gnn_fused<<<TT / 3, 512, FUSE_SMEM_BYTES>>>(b2, out);
}

// round 9
// speedup vs baseline: 1.4616x; 1.4616x over previous
#include <cuda_runtime.h>

#define BB 16
#define LL 24
#define NN 256
#define EE 4096
#define TT (BB*LL)      // 384 graphs
#define BN (BB*NN)      // 4096 LSTM samples
#define S_MAX 14        // samples per LSTM block (293 blocks, 2 blocks/SM)
#define PN 268          // padded node stride for transposed X

// ---------------- packed f32x2 helpers ----------------
__device__ __forceinline__ unsigned long long packf2(float lo, float hi) {
    unsigned long long r;
    asm("mov.b64 %0,{%1,%2};" : "=l"(r) : "f"(lo), "f"(hi));
    return r;
}
__device__ __forceinline__ void unpackf2(unsigned long long v, float& lo, float& hi) {
    asm("mov.b64 {%0,%1},%2;" : "=f"(lo), "=f"(hi) : "l"(v));
}
__device__ __forceinline__ void ffma2(unsigned long long& d, unsigned long long a,
                                      unsigned long long b) {
    asm("fma.rn.f32x2 %0,%1,%2,%0;" : "+l"(d) : "l"(a), "l"(b));
}
__device__ __forceinline__ float tanha(float x) {
    float r; asm("tanh.approx.f32 %0,%1;" : "=f"(r) : "f"(x)); return r;
}
__device__ __forceinline__ float fsig(float x) { return 0.5f * tanha(0.5f * x) + 0.5f; }

// ---------------- device scratch ----------------
__device__ float g_Hout[TT * NN * 64];     // 25 MB
__device__ float g_M1[4096];
__device__ float g_M2[4096];
__device__ float g_Wc[4096];
__device__ float g_G0[64], g_G1[64], g_Gb[64];
__device__ float g_s0v[NN], g_s1v[NN];
__device__ int   g_deg[NN];
__device__ int   g_off[NN + 1];
__device__ int   g_src[EE];

// ---------------- merged setup: block 0 = CSR/graph, blocks 1..65 = weight folds ----
__global__ void setup_all(const int* __restrict__ conn,
                          const float* __restrict__ city_w,
                          const float* __restrict__ W1,   // [130,64]
                          const float* __restrict__ b1,   // [64]
                          const float* __restrict__ W2)   // [128,64]
{
    int t = threadIdx.x;
    if (blockIdx.x == 0) {
        __shared__ float s0[NN], s1[NN];
        __shared__ int degs[NN], cur[NN], scan[NN];

        if (t < NN) { s0[t] = 0.f; s1[t] = 0.f; degs[t] = 0; }
        __syncthreads();

        const int* row = conn;
        const int* col = conn + EE;
#pragma unroll
        for (int u = 0; u < EE / 1024; u++) {
            int e = u * 1024 + t;
            int c = col[e];
            atomicAdd(&degs[c], 1);
            atomicAdd(&s0[c], city_w[2 * e + 0]);
            atomicAdd(&s1[c], city_w[2 * e + 1]);
        }
        __syncthreads();

        if (t < NN) scan[t] = degs[t];
        __syncthreads();
        for (int d = 1; d < NN; d <<= 1) {
            int v = (t < NN && t >= d) ? scan[t - d] : 0;
            __syncthreads();
            if (t < NN) scan[t] += v;
            __syncthreads();
        }
        if (t < NN) {
            int excl = scan[t] - degs[t];
            g_off[t] = excl;
            cur[t] = excl;
            g_deg[t] = degs[t];
            g_s0v[t] = s0[t];
            g_s1v[t] = s1[t];
            if (t == NN - 1) g_off[NN] = scan[NN - 1];
        }
        __syncthreads();
#pragma unroll
        for (int u = 0; u < EE / 1024; u++) {
            int e = u * 1024 + t;
            int c = col[e];
            int p = atomicAdd(&cur[c], 1);
            g_src[p] = row[e];
        }
    } else {
        int k = blockIdx.x - 1;
        int c = t;
        const float* W2b = W2 + 4096;
        if (k < 64) {
            __shared__ float w1a[64], w1b[64];
            if (c < 64) { w1a[c] = W1[k * 64 + c]; w1b[c] = W1[4096 + k * 64 + c]; }
            __syncthreads();
            if (c < 64) {
                float p0 = 0.f, p1 = 0.f, p2 = 0.f, p3 = 0.f;
                float q0 = 0.f, q1 = 0.f, q2 = 0.f, q3 = 0.f;
#pragma unroll
                for (int j = 0; j < 64; j += 4) {
                    float v0 = W2b[(j + 0) * 64 + c];
                    float v1 = W2b[(j + 1) * 64 + c];
                    float v2 = W2b[(j + 2) * 64 + c];
                    float v3 = W2b[(j + 3) * 64 + c];
                    p0 += w1a[j + 0] * v0; q0 += w1b[j + 0] * v0;
                    p1 += w1a[j + 1] * v1; q1 += w1b[j + 1] * v1;
                    p2 += w1a[j + 2] * v2; q2 += w1b[j + 2] * v2;
                    p3 += w1a[j + 3] * v3; q3 += w1b[j + 3] * v3;
                }
                float a1 = (p0 + p1) + (p2 + p3);
                float a2 = (q0 + q1) + (q2 + q3);
                g_M1[k * 64 + c] = a1;
                g_M2[k * 64 + c] = a2;
                g_Wc[k * 64 + c] = W2[k * 64 + c] + a2;
            }
        } else if (c < 64) {
            float a0 = 0.f, a1 = 0.f, ab = 0.f;
#pragma unroll 8
            for (int j = 0; j < 64; j++) {
                float w2 = W2b[j * 64 + c];
                a0 += W1[128 * 64 + j] * w2;
                a1 += W1[129 * 64 + j] * w2;
                ab += b1[j] * w2;
            }
            g_G0[c] = a0; g_G1[c] = a1; g_Gb[c] = ab;
        }
    }
}

// ---------------- LSTM: 256 threads, 14 samples, 2 blocks/SM, 2-sample interleave ----
__global__ void __launch_bounds__(256, 2)
lstm_kernel(const float* __restrict__ aqi,
            const float* __restrict__ embW,
            const float* __restrict__ embB,
            const float* __restrict__ Wih,
            const float* __restrict__ Whh,
            const float* __restrict__ bih,
            const float* __restrict__ bhh)
{
    __shared__ __align__(16) float hS[S_MAX][64];
    __shared__ __align__(16) float cS[S_MAX][64];
    __shared__ __align__(16) float gS[S_MAX][256];
    __shared__ float aS[S_MAX][LL];

    int tid = threadIdx.x;          // gate row r
    int m0  = blockIdx.x * S_MAX;
    int cnt = BN - m0; if (cnt > S_MAX) cnt = S_MAX;   // always even (14 or 8)

    unsigned long long w2[32];
    {
        const ulonglong2* wr = (const ulonglong2*)(Whh + tid * 64);
#pragma unroll
        for (int i = 0; i < 16; i++) {
            ulonglong2 v = wr[i];
            w2[2 * i] = v.x; w2[2 * i + 1] = v.y;
        }
    }
    float A = 0.f, Bc = 0.f;
#pragma unroll
    for (int j = 0; j < 16; j++) {
        float wi = Wih[tid * 16 + j];
        A  += wi * embW[j];
        Bc += wi * embB[j];
    }
    Bc += bih[tid] + bhh[tid];

    for (int idx = tid; idx < cnt * LL; idx += 256) {
        int s = idx / LL, l = idx % LL;
        int m = m0 + s; int b = m >> 8; int n = m & 255;
        aS[s][l] = aqi[(b * LL + l) * NN + n];
    }
    for (int idx = tid; idx < cnt * 64; idx += 256) {
        ((float*)hS)[idx] = 0.f; ((float*)cS)[idx] = 0.f;
    }
    __syncthreads();

    int se = tid >> 4;               // 0..15
    int j0 = (tid & 15) << 2;

    for (int l = 0; l < LL; l++) {
        // two samples interleaved: doubles independent FFMA2 streams per thread
        for (int s = 0; s < cnt; s += 2) {
            unsigned long long a0 = 0ull, a1 = 0ull, a2 = 0ull, a3 = 0ull;
            unsigned long long b0 = 0ull, b1 = 0ull, b2 = 0ull, b3 = 0ull;
            const ulonglong2* hpA = (const ulonglong2*)hS[s];
            const ulonglong2* hpB = (const ulonglong2*)hS[s + 1];
#pragma unroll
            for (int i = 0; i < 8; i++) {
                ulonglong2 ha0 = hpA[2 * i];
                ulonglong2 hb0 = hpB[2 * i];
                ulonglong2 ha1 = hpA[2 * i + 1];
                ulonglong2 hb1 = hpB[2 * i + 1];
                ffma2(a0, ha0.x, w2[4 * i + 0]);
                ffma2(b0, hb0.x, w2[4 * i + 0]);
                ffma2(a1, ha0.y, w2[4 * i + 1]);
                ffma2(b1, hb0.y, w2[4 * i + 1]);
                ffma2(a2, ha1.x, w2[4 * i + 2]);
                ffma2(b2, hb1.x, w2[4 * i + 2]);
                ffma2(a3, ha1.y, w2[4 * i + 3]);
                ffma2(b3, hb1.y, w2[4 * i + 3]);
            }
            float x0, x1, x2, x3, x4, x5, x6, x7;
            unpackf2(a0, x0, x1); unpackf2(a1, x2, x3);
            unpackf2(a2, x4, x5); unpackf2(a3, x6, x7);
            gS[s][tid] = aS[s][l] * A + Bc +
                         (((x0 + x1) + (x2 + x3)) + ((x4 + x5) + (x6 + x7)));
            unpackf2(b0, x0, x1); unpackf2(b1, x2, x3);
            unpackf2(b2, x4, x5); unpackf2(b3, x6, x7);
            gS[s + 1][tid] = aS[s + 1][l] * A + Bc +
                             (((x0 + x1) + (x2 + x3)) + ((x4 + x5) + (x6 + x7)));
        }
        __syncthreads();
        if (se < cnt) {
            float4 gi = *(const float4*)&gS[se][j0];
            float4 gf = *(const float4*)&gS[se][64 + j0];
            float4 gg = *(const float4*)&gS[se][128 + j0];
            float4 go = *(const float4*)&gS[se][192 + j0];
            float4 c4 = *(const float4*)&cS[se][j0];
            c4.x = fsig(gf.x) * c4.x + fsig(gi.x) * tanha(gg.x);
            c4.y = fsig(gf.y) * c4.y + fsig(gi.y) * tanha(gg.y);
            c4.z = fsig(gf.z) * c4.z + fsig(gi.z) * tanha(gg.z);
            c4.w = fsig(gf.w) * c4.w + fsig(gi.w) * tanha(gg.w);
            float4 h4;
            h4.x = fsig(go.x) * tanha(c4.x);
            h4.y = fsig(go.y) * tanha(c4.y);
            h4.z = fsig(go.z) * tanha(c4.z);
            h4.w = fsig(go.w) * tanha(c4.w);
            *(float4*)&cS[se][j0] = c4;
            *(float4*)&hS[se][j0] = h4;
            int me = m0 + se; int be = me >> 8; int ne = me & 255;
            *(float4*)(g_Hout + ((size_t)(be * LL + l) * NN + ne) * 64 + j0) = h4;
        }
        __syncthreads();
    }
}

// ---------------- fused GNN: 128 blocks x 3 graphs, 512 threads ----------------
#define FUSE_SMEM_FLOATS (64 * PN + 16384 + 4096 + 4096 + 64 + 192 + 512 + 4096 + 257 + 256)
#define FUSE_SMEM_BYTES  (FUSE_SMEM_FLOATS * 4)

__global__ void __launch_bounds__(512, 1)
gnn_fused(const float* __restrict__ b2, float* __restrict__ out)
{
    extern __shared__ __align__(16) float sm[];
    float* Xk  = sm;                       // 64*PN (transposed X; aliased as Zbuf later)
    float* Vs  = Xk + 64 * PN;             // 256*64
    float* W1s = Vs + 16384;               // 4096
    float* Wcs = W1s + 4096;               // 4096
    float* b2s = Wcs + 4096;               // 64
    float* G0s = b2s + 64;                 // 64
    float* G1s = G0s + 64;                 // 64
    float* Gbs = G1s + 64;                 // 64
    float* s0S = Gbs + 64;                 // 256
    float* s1S = s0S + 256;                // 256
    int* srcS  = (int*)(s1S + 256);        // 4096
    int* offS  = srcS + EE;                // 257
    int* degS  = offS + NN + 1;            // 256

    int tid = threadIdx.x;
    for (int i = tid; i < 4096; i += 512) {
        W1s[i] = g_M1[i];
        Wcs[i] = g_Wc[i];
        srcS[i] = g_src[i];
    }
    if (tid < 64) {
        b2s[tid] = b2[tid];
        G0s[tid] = g_G0[tid]; G1s[tid] = g_G1[tid]; Gbs[tid] = g_Gb[tid];
    }
    if (tid < 256) { s0S[tid] = g_s0v[tid]; s1S[tid] = g_s1v[tid]; degS[tid] = g_deg[tid]; }
    if (tid < 257) offS[tid] = g_off[tid];

    int cg = tid & 15, ng = tid >> 4;
    int c0 = cg * 4, n0 = ng * 8;
    int lane = tid & 31, warp = tid >> 5;

    for (int g = 0; g < 3; g++) {
        int t = blockIdx.x * 3 + g;
        const float* Xg = g_Hout + (size_t)t * NN * 64;
        for (int idx = tid; idx < NN * 64; idx += 512) {
            int n = idx >> 6, c = idx & 63;
            Xk[c * PN + n] = Xg[idx];
        }
        __syncthreads();   // X ready

        unsigned long long acc1[16], acc2[16];
#pragma unroll
        for (int i = 0; i < 16; i++) { acc1[i] = 0ull; acc2[i] = 0ull; }

        // ---- fused mm1 (V = X@M1) + mm2 (Z = X@Wc) : X read once ----
#pragma unroll 4
        for (int k = 0; k < 64; k++) {
            float4 xa = *(const float4*)(Xk + k * PN + n0);
            float4 xb = *(const float4*)(Xk + k * PN + n0 + 4);
            ulonglong2 w1 = *(const ulonglong2*)(W1s + k * 64 + c0);
            ulonglong2 wc = *(const ulonglong2*)(Wcs + k * 64 + c0);
            unsigned long long x;
            x = packf2(xa.x, xa.x);
            ffma2(acc1[0],  x, w1.x); ffma2(acc1[1],  x, w1.y);
            ffma2(acc2[0],  x, wc.x); ffma2(acc2[1],  x, wc.y);
            x = packf2(xa.y, xa.y);
            ffma2(acc1[2],  x, w1.x); ffma2(acc1[3],  x, w1.y);
            ffma2(acc2[2],  x, wc.x); ffma2(acc2[3],  x, wc.y);
            x = packf2(xa.z, xa.z);
            ffma2(acc1[4],  x, w1.x); ffma2(acc1[5],  x, w1.y);
            ffma2(acc2[4],  x, wc.x); ffma2(acc2[5],  x, wc.y);
            x = packf2(xa.w, xa.w);
            ffma2(acc1[6],  x, w1.x); ffma2(acc1[7],  x, w1.y);
            ffma2(acc2[6],  x, wc.x); ffma2(acc2[7],  x, wc.y);
            x = packf2(xb.x, xb.x);
            ffma2(acc1[8],  x, w1.x); ffma2(acc1[9],  x, w1.y);
            ffma2(acc2[8],  x, wc.x); ffma2(acc2[9],  x, wc.y);
            x = packf2(xb.y, xb.y);
            ffma2(acc1[10], x, w1.x); ffma2(acc1[11], x, w1.y);
            ffma2(acc2[10], x, wc.x); ffma2(acc2[11], x, wc.y);
            x = packf2(xb.z, xb.z);
            ffma2(acc1[12], x, w1.x); ffma2(acc1[13], x, w1.y);
            ffma2(acc2[12], x, wc.x); ffma2(acc2[13], x, wc.y);
            x = packf2(xb.w, xb.w);
            ffma2(acc1[14], x, w1.x); ffma2(acc1[15], x, w1.y);
            ffma2(acc2[14], x, wc.x); ffma2(acc2[15], x, wc.y);
        }

        // V -> Vs
#pragma unroll
        for (int n = 0; n < 8; n++) {
            float4 v;
            unpackf2(acc1[2 * n], v.x, v.y);
            unpackf2(acc1[2 * n + 1], v.z, v.w);
            *(float4*)(Vs + (n0 + n) * 64 + c0) = v;
        }

        // Z = acc2 + b2 (deg==0 rare path: subtract X@M2)
        float4 bb = *(const float4*)(b2s + c0);
        float4 z[8];
#pragma unroll
        for (int n = 0; n < 8; n++) {
            unpackf2(acc2[2 * n], z[n].x, z[n].y);
            unpackf2(acc2[2 * n + 1], z[n].z, z[n].w);
            z[n].x += bb.x; z[n].y += bb.y; z[n].z += bb.z; z[n].w += bb.w;
            if (degS[n0 + n] == 0) {
                float s0c = 0.f, s1c = 0.f, s2c = 0.f, s3c = 0.f;
                for (int k = 0; k < 64; k++) {
                    float xv = Xk[k * PN + n0 + n];
                    s0c += xv * g_M2[k * 64 + c0 + 0];
                    s1c += xv * g_M2[k * 64 + c0 + 1];
                    s2c += xv * g_M2[k * 64 + c0 + 2];
                    s3c += xv * g_M2[k * 64 + c0 + 3];
                }
                z[n].x -= s0c; z[n].y -= s1c; z[n].z -= s2c; z[n].w -= s3c;
            }
        }
        __syncthreads();   // all Xk reads done; Vs complete

        float* Zb = Xk;    // reuse X space for Z (node-major, stride 64)
#pragma unroll
        for (int n = 0; n < 8; n++)
            *(float4*)(Zb + (n0 + n) * 64 + c0) = z[n];
        __syncthreads();   // Zb ready

        // ---- gather: out = Z + (sum_in V + Cp)/deg ----
        for (int n = warp; n < NN; n += 16) {
            int lo = offS[n], hi = offS[n + 1];
            float a0 = 0.f, a1 = 0.f;
            int e = lo;
            for (; e + 4 <= hi; e += 4) {
                int i0 = srcS[e], i1 = srcS[e + 1], i2 = srcS[e + 2], i3 = srcS[e + 3];
                a0 += Vs[i0 * 64 + lane]      + Vs[i1 * 64 + lane]
                    + Vs[i2 * 64 + lane]      + Vs[i3 * 64 + lane];
                a1 += Vs[i0 * 64 + 32 + lane] + Vs[i1 * 64 + 32 + lane]
                    + Vs[i2 * 64 + 32 + lane] + Vs[i3 * 64 + 32 + lane];
            }
            for (; e < hi; e++) {
                int i0 = srcS[e];
                a0 += Vs[i0 * 64 + lane];
                a1 += Vs[i0 * 64 + 32 + lane];
            }
            float degf = (float)(hi - lo);
            float dinv = 1.f / fmaxf(degf, 1.f);
            float sn0 = s0S[n], sn1 = s1S[n];
            float cp0 = sn0 * G0s[lane]      + sn1 * G1s[lane]      + degf * Gbs[lane];
            float cp1 = sn0 * G0s[32 + lane] + sn1 * G1s[32 + lane] + degf * Gbs[32 + lane];
            float* op = out + ((size_t)t * NN + n) * 64;
            op[lane]      = Zb[n * 64 + lane]      + (a0 + cp0) * dinv;
            op[32 + lane] = Zb[n * 64 + 32 + lane] + (a1 + cp1) * dinv;
        }
        __syncthreads();   // protect Xk/Vs before next graph
    }
}

// ---------------- launch ----------------
extern "C" void kernel_launch(void* const* d_in, const int* in_sizes, int n_in,
                              void* d_out, int out_size)
{
    const float* aqi  = (const float*)d_in[0];
    const int*   conn = (const int*)  d_in[1];
    const float* cw   = (const float*)d_in[2];
    const float* embW = (const float*)d_in[3];
    const float* embB = (const float*)d_in[4];
    const float* Wih  = (const float*)d_in[5];
    const float* Whh  = (const float*)d_in[6];
    const float* bih  = (const float*)d_in[7];
    const float* bhh  = (const float*)d_in[8];
    const float* W1   = (const float*)d_in[9];
    const float* b1   = (const float*)d_in[10];
    const float* W2   = (const float*)d_in[11];
    const float* b2   = (const float*)d_in[12];
    float* out = (float*)d_out;

    int lstm_blocks = (BN + S_MAX - 1) / S_MAX;   // 293
    lstm_kernel<<<lstm_blocks, 256>>>(aqi, embW, embB, Wih, Whh, bih, bhh);
    setup_all<<<66, 1024>>>(conn, cw, W1, b1, W2);
    cudaFuncSetAttribute(gnn_fused, cudaFuncAttributeMaxDynamicSharedMemorySize,
                         FUSE_SMEM_BYTES);
    gnn_fused<<<TT / 3, 512, FUSE_SMEM_BYTES>>>(b2, out);
}

// round 10
// speedup vs baseline: 1.5729x; 1.0762x over previous
#include <cuda_runtime.h>

#define BB 16
#define LL 24
#define NN 256
#define EE 4096
#define TT (BB*LL)      // 384 graphs
#define BN (BB*NN)      // 4096 LSTM samples
#define PN 268          // padded node stride for transposed X (GNN)

// ---------------- packed f32x2 helpers ----------------
__device__ __forceinline__ unsigned long long packf2(float lo, float hi) {
    unsigned long long r;
    asm("mov.b64 %0,{%1,%2};" : "=l"(r) : "f"(lo), "f"(hi));
    return r;
}
__device__ __forceinline__ void unpackf2(unsigned long long v, float& lo, float& hi) {
    asm("mov.b64 {%0,%1},%2;" : "=f"(lo), "=f"(hi) : "l"(v));
}
__device__ __forceinline__ void ffma2(unsigned long long& d, unsigned long long a,
                                      unsigned long long b) {
    asm("fma.rn.f32x2 %0,%1,%2,%0;" : "+l"(d) : "l"(a), "l"(b));
}
__device__ __forceinline__ float tanha(float x) {
    float r; asm("tanh.approx.f32 %0,%1;" : "=f"(r) : "f"(x)); return r;
}
__device__ __forceinline__ float fsig(float x) { return 0.5f * tanha(0.5f * x) + 0.5f; }

// ---------------- device scratch ----------------
__device__ float g_Hout[TT * NN * 64];     // 25 MB
__device__ float g_WhhT[64 * 256];         // Whh transposed [k][r]
__device__ float g_Af[256], g_Bf[256];     // folded input weights/bias per gate row
__device__ float g_M1[4096];
__device__ float g_M2[4096];
__device__ float g_Wc[4096];
__device__ float g_G0[64], g_G1[64], g_Gb[64];
__device__ float g_s0v[NN], g_s1v[NN];
__device__ int   g_deg[NN];
__device__ int   g_off[NN + 1];
__device__ int   g_src[EE];

// ---------------- merged setup ----------------
// block 0: graph/CSR; blocks 1..65: GNN weight folds; 66: Whh transpose; 67: Af/Bf
__global__ void setup_all(const int* __restrict__ conn,
                          const float* __restrict__ city_w,
                          const float* __restrict__ W1,    // [130,64]
                          const float* __restrict__ b1,    // [64]
                          const float* __restrict__ W2,    // [128,64]
                          const float* __restrict__ Whh,   // [256,64]
                          const float* __restrict__ Wih,   // [256,16]
                          const float* __restrict__ embW,  // [16]
                          const float* __restrict__ embB,  // [16]
                          const float* __restrict__ bih,   // [256]
                          const float* __restrict__ bhh)   // [256]
{
    int t = threadIdx.x;
    if (blockIdx.x == 0) {
        __shared__ float s0[NN], s1[NN];
        __shared__ int degs[NN], cur[NN], scan[NN];

        if (t < NN) { s0[t] = 0.f; s1[t] = 0.f; degs[t] = 0; }
        __syncthreads();

        const int* row = conn;
        const int* col = conn + EE;
#pragma unroll
        for (int u = 0; u < EE / 1024; u++) {
            int e = u * 1024 + t;
            int c = col[e];
            atomicAdd(&degs[c], 1);
            atomicAdd(&s0[c], city_w[2 * e + 0]);
            atomicAdd(&s1[c], city_w[2 * e + 1]);
        }
        __syncthreads();

        if (t < NN) scan[t] = degs[t];
        __syncthreads();
        for (int d = 1; d < NN; d <<= 1) {
            int v = (t < NN && t >= d) ? scan[t - d] : 0;
            __syncthreads();
            if (t < NN) scan[t] += v;
            __syncthreads();
        }
        if (t < NN) {
            int excl = scan[t] - degs[t];
            g_off[t] = excl;
            cur[t] = excl;
            g_deg[t] = degs[t];
            g_s0v[t] = s0[t];
            g_s1v[t] = s1[t];
            if (t == NN - 1) g_off[NN] = scan[NN - 1];
        }
        __syncthreads();
#pragma unroll
        for (int u = 0; u < EE / 1024; u++) {
            int e = u * 1024 + t;
            int c = col[e];
            int p = atomicAdd(&cur[c], 1);
            g_src[p] = row[e];
        }
    } else if (blockIdx.x <= 65) {
        int k = blockIdx.x - 1;
        int c = t;
        const float* W2b = W2 + 4096;
        if (k < 64) {
            __shared__ float w1a[64], w1b[64];
            if (c < 64) { w1a[c] = W1[k * 64 + c]; w1b[c] = W1[4096 + k * 64 + c]; }
            __syncthreads();
            if (c < 64) {
                float p0 = 0.f, p1 = 0.f, p2 = 0.f, p3 = 0.f;
                float q0 = 0.f, q1 = 0.f, q2 = 0.f, q3 = 0.f;
#pragma unroll
                for (int j = 0; j < 64; j += 4) {
                    float v0 = W2b[(j + 0) * 64 + c];
                    float v1 = W2b[(j + 1) * 64 + c];
                    float v2 = W2b[(j + 2) * 64 + c];
                    float v3 = W2b[(j + 3) * 64 + c];
                    p0 += w1a[j + 0] * v0; q0 += w1b[j + 0] * v0;
                    p1 += w1a[j + 1] * v1; q1 += w1b[j + 1] * v1;
                    p2 += w1a[j + 2] * v2; q2 += w1b[j + 2] * v2;
                    p3 += w1a[j + 3] * v3; q3 += w1b[j + 3] * v3;
                }
                float a1 = (p0 + p1) + (p2 + p3);
                float a2 = (q0 + q1) + (q2 + q3);
                g_M1[k * 64 + c] = a1;
                g_M2[k * 64 + c] = a2;
                g_Wc[k * 64 + c] = W2[k * 64 + c] + a2;
            }
        } else if (c < 64) {
            float a0 = 0.f, a1 = 0.f, ab = 0.f;
#pragma unroll 8
            for (int j = 0; j < 64; j++) {
                float w2 = W2b[j * 64 + c];
                a0 += W1[128 * 64 + j] * w2;
                a1 += W1[129 * 64 + j] * w2;
                ab += b1[j] * w2;
            }
            g_G0[c] = a0; g_G1[c] = a1; g_Gb[c] = ab;
        }
    } else if (blockIdx.x == 66) {
        // transpose Whh -> [k][r], coalesced writes
        for (int idx = t; idx < 64 * 256; idx += 1024) {
            int k = idx >> 8, r = idx & 255;
            g_WhhT[idx] = Whh[r * 64 + k];
        }
    } else {
        if (t < 256) {
            float A = 0.f, B = 0.f;
#pragma unroll
            for (int j = 0; j < 16; j++) {
                float wi = Wih[t * 16 + j];
                A += wi * embW[j];
                B += wi * embB[j];
            }
            g_Af[t] = A;
            g_Bf[t] = B + bih[t] + bhh[t];
        }
    }
}

// ---------------- LSTM v2: smem-weight register-tiled GEMM ----------------
// 128 threads, S=16 samples, 256 blocks (2/SM). Tile: 8 samples x 4 gate-cols.
#define S_L 16
#define HTS 36                         // hT stride [k][36]
#define GSS 260                        // gS stride [s][260]
#define LSMEM_FLOATS (16384 + 64*HTS + S_L*GSS + 256 + 256 + S_L*LL)
#define LSMEM_BYTES  (LSMEM_FLOATS * 4)

__global__ void __launch_bounds__(128)
lstm_kernel(const float* __restrict__ aqi)
{
    extern __shared__ __align__(16) float ls[];
    float* WT = ls;                    // [k][256]  64KB
    float* hT = ls + 16384;            // [k][HTS]
    float* gS = hT + 64 * HTS;         // [s][GSS]
    float* Af = gS + S_L * GSS;        // 256
    float* Bf = Af + 256;              // 256
    float* aS = Bf + 256;              // [s][LL]

    int tid = threadIdx.x;
    int m0 = blockIdx.x * S_L;
    int b = m0 >> 8, n0 = m0 & 255;

    // stage weights (coalesced, conflict-free)
    {
        float4* d = (float4*)WT;
        const float4* s4 = (const float4*)g_WhhT;
        for (int i = tid; i < 4096; i += 128) d[i] = s4[i];
    }
    for (int i = tid; i < 64 * HTS; i += 128) hT[i] = 0.f;
    for (int i = tid; i < 256; i += 128) { Af[i] = g_Af[i]; Bf[i] = g_Bf[i]; }
    for (int i = tid; i < S_L * LL; i += 128) {
        int s = i / LL, l = i % LL;
        aS[i] = aqi[(b * LL + l) * NN + (n0 + s)];
    }
    __syncthreads();

    // matvec mapping
    int sg = tid >> 6, cg = tid & 63;
    int s0 = sg * 8, c0 = cg * 4;
    // epilogue mapping
    int se = tid & 15, j0 = (tid >> 4) * 8;

    float c_reg[8];
#pragma unroll
    for (int i = 0; i < 8; i++) c_reg[i] = 0.f;
    float* hout = g_Hout + ((size_t)(b * LL) * NN + (n0 + se)) * 64 + j0;

    for (int l = 0; l < LL; l++) {
        unsigned long long acc[16];   // [sample-pair 0..3][col 0..3]
#pragma unroll
        for (int i = 0; i < 16; i++) acc[i] = 0ull;

#pragma unroll 4
        for (int k = 0; k < 64; k++) {
            ulonglong2 hA = *(const ulonglong2*)(hT + k * HTS + s0);      // s0..s0+3
            ulonglong2 hB = *(const ulonglong2*)(hT + k * HTS + s0 + 4);  // s0+4..s0+7
            float4 w4 = *(const float4*)(WT + k * 256 + c0);
            unsigned long long w0 = packf2(w4.x, w4.x);
            unsigned long long w1 = packf2(w4.y, w4.y);
            unsigned long long w2 = packf2(w4.z, w4.z);
            unsigned long long w3 = packf2(w4.w, w4.w);
            ffma2(acc[0],  hA.x, w0); ffma2(acc[1],  hA.x, w1);
            ffma2(acc[2],  hA.x, w2); ffma2(acc[3],  hA.x, w3);
            ffma2(acc[4],  hA.y, w0); ffma2(acc[5],  hA.y, w1);
            ffma2(acc[6],  hA.y, w2); ffma2(acc[7],  hA.y, w3);
            ffma2(acc[8],  hB.x, w0); ffma2(acc[9],  hB.x, w1);
            ffma2(acc[10], hB.x, w2); ffma2(acc[11], hB.x, w3);
            ffma2(acc[12], hB.y, w0); ffma2(acc[13], hB.y, w1);
            ffma2(acc[14], hB.y, w2); ffma2(acc[15], hB.y, w3);
        }

        // add folded input + bias, store gates
        {
            float4 af = *(const float4*)(Af + c0);
            float4 bf = *(const float4*)(Bf + c0);
#pragma unroll
            for (int j = 0; j < 4; j++) {     // sample pair j -> samples s0+2j, s0+2j+1
                float4 glo, ghi;
                unpackf2(acc[4 * j + 0], glo.x, ghi.x);
                unpackf2(acc[4 * j + 1], glo.y, ghi.y);
                unpackf2(acc[4 * j + 2], glo.z, ghi.z);
                unpackf2(acc[4 * j + 3], glo.w, ghi.w);
                float alo = aS[(s0 + 2 * j) * LL + l];
                float ahi = aS[(s0 + 2 * j + 1) * LL + l];
                glo.x += alo * af.x + bf.x; glo.y += alo * af.y + bf.y;
                glo.z += alo * af.z + bf.z; glo.w += alo * af.w + bf.w;
                ghi.x += ahi * af.x + bf.x; ghi.y += ahi * af.y + bf.y;
                ghi.z += ahi * af.z + bf.z; ghi.w += ahi * af.w + bf.w;
                *(float4*)(gS + (s0 + 2 * j) * GSS + c0) = glo;
                *(float4*)(gS + (s0 + 2 * j + 1) * GSS + c0) = ghi;
            }
        }
        __syncthreads();

        // epilogue: thread owns (sample se, channels j0..j0+7); c in registers
        {
            const float* gr = gS + se * GSS;
            float4 gi0 = *(const float4*)(gr + j0);
            float4 gi1 = *(const float4*)(gr + j0 + 4);
            float4 gf0 = *(const float4*)(gr + 64 + j0);
            float4 gf1 = *(const float4*)(gr + 64 + j0 + 4);
            float4 gg0 = *(const float4*)(gr + 128 + j0);
            float4 gg1 = *(const float4*)(gr + 128 + j0 + 4);
            float4 go0 = *(const float4*)(gr + 192 + j0);
            float4 go1 = *(const float4*)(gr + 192 + j0 + 4);

            float hv[8];
            float gi[8] = {gi0.x, gi0.y, gi0.z, gi0.w, gi1.x, gi1.y, gi1.z, gi1.w};
            float gf[8] = {gf0.x, gf0.y, gf0.z, gf0.w, gf1.x, gf1.y, gf1.z, gf1.w};
            float gg[8] = {gg0.x, gg0.y, gg0.z, gg0.w, gg1.x, gg1.y, gg1.z, gg1.w};
            float go[8] = {go0.x, go0.y, go0.z, go0.w, go1.x, go1.y, go1.z, go1.w};
#pragma unroll
            for (int i = 0; i < 8; i++) {
                float cn = fsig(gf[i]) * c_reg[i] + fsig(gi[i]) * tanha(gg[i]);
                c_reg[i] = cn;
                hv[i] = fsig(go[i]) * tanha(cn);
            }
#pragma unroll
            for (int i = 0; i < 8; i++)
                hT[(j0 + i) * HTS + se] = hv[i];
            float4 o0 = {hv[0], hv[1], hv[2], hv[3]};
            float4 o1 = {hv[4], hv[5], hv[6], hv[7]};
            *(float4*)(hout + (size_t)l * NN * 64) = o0;
            *(float4*)(hout + (size_t)l * NN * 64 + 4) = o1;
        }
        __syncthreads();
    }
}

// ---------------- fused GNN: 128 blocks x 3 graphs, 512 threads (unchanged) ------
#define FUSE_SMEM_FLOATS (64 * PN + 16384 + 4096 + 4096 + 64 + 192 + 512 + 4096 + 257 + 256)
#define FUSE_SMEM_BYTES  (FUSE_SMEM_FLOATS * 4)

__global__ void __launch_bounds__(512, 1)
gnn_fused(const float* __restrict__ b2, float* __restrict__ out)
{
    extern __shared__ __align__(16) float sm[];
    float* Xk  = sm;                       // 64*PN (transposed X; aliased as Zbuf later)
    float* Vs  = Xk + 64 * PN;             // 256*64
    float* W1s = Vs + 16384;               // 4096
    float* Wcs = W1s + 4096;               // 4096
    float* b2s = Wcs + 4096;               // 64
    float* G0s = b2s + 64;                 // 64
    float* G1s = G0s + 64;                 // 64
    float* Gbs = G1s + 64;                 // 64
    float* s0S = Gbs + 64;                 // 256
    float* s1S = s0S + 256;                // 256
    int* srcS  = (int*)(s1S + 256);        // 4096
    int* offS  = srcS + EE;                // 257
    int* degS  = offS + NN + 1;            // 256

    int tid = threadIdx.x;
    for (int i = tid; i < 4096; i += 512) {
        W1s[i] = g_M1[i];
        Wcs[i] = g_Wc[i];
        srcS[i] = g_src[i];
    }
    if (tid < 64) {
        b2s[tid] = b2[tid];
        G0s[tid] = g_G0[tid]; G1s[tid] = g_G1[tid]; Gbs[tid] = g_Gb[tid];
    }
    if (tid < 256) { s0S[tid] = g_s0v[tid]; s1S[tid] = g_s1v[tid]; degS[tid] = g_deg[tid]; }
    if (tid < 257) offS[tid] = g_off[tid];

    int cg = tid & 15, ng = tid >> 4;
    int c0 = cg * 4, n0 = ng * 8;
    int lane = tid & 31, warp = tid >> 5;

    for (int g = 0; g < 3; g++) {
        int t = blockIdx.x * 3 + g;
        const float* Xg = g_Hout + (size_t)t * NN * 64;
        for (int idx = tid; idx < NN * 64; idx += 512) {
            int n = idx >> 6, c = idx & 63;
            Xk[c * PN + n] = Xg[idx];
        }
        __syncthreads();   // X ready

        unsigned long long acc1[16], acc2[16];
#pragma unroll
        for (int i = 0; i < 16; i++) { acc1[i] = 0ull; acc2[i] = 0ull; }

#pragma unroll 4
        for (int k = 0; k < 64; k++) {
            float4 xa = *(const float4*)(Xk + k * PN + n0);
            float4 xb = *(const float4*)(Xk + k * PN + n0 + 4);
            ulonglong2 w1 = *(const ulonglong2*)(W1s + k * 64 + c0);
            ulonglong2 wc = *(const ulonglong2*)(Wcs + k * 64 + c0);
            unsigned long long x;
            x = packf2(xa.x, xa.x);
            ffma2(acc1[0],  x, w1.x); ffma2(acc1[1],  x, w1.y);
            ffma2(acc2[0],  x, wc.x); ffma2(acc2[1],  x, wc.y);
            x = packf2(xa.y, xa.y);
            ffma2(acc1[2],  x, w1.x); ffma2(acc1[3],  x, w1.y);
            ffma2(acc2[2],  x, wc.x); ffma2(acc2[3],  x, wc.y);
            x = packf2(xa.z, xa.z);
            ffma2(acc1[4],  x, w1.x); ffma2(acc1[5],  x, w1.y);
            ffma2(acc2[4],  x, wc.x); ffma2(acc2[5],  x, wc.y);
            x = packf2(xa.w, xa.w);
            ffma2(acc1[6],  x, w1.x); ffma2(acc1[7],  x, w1.y);
            ffma2(acc2[6],  x, wc.x); ffma2(acc2[7],  x, wc.y);
            x = packf2(xb.x, xb.x);
            ffma2(acc1[8],  x, w1.x); ffma2(acc1[9],  x, w1.y);
            ffma2(acc2[8],  x, wc.x); ffma2(acc2[9],  x, wc.y);
            x = packf2(xb.y, xb.y);
            ffma2(acc1[10], x, w1.x); ffma2(acc1[11], x, w1.y);
            ffma2(acc2[10], x, wc.x); ffma2(acc2[11], x, wc.y);
            x = packf2(xb.z, xb.z);
            ffma2(acc1[12], x, w1.x); ffma2(acc1[13], x, w1.y);
            ffma2(acc2[12], x, wc.x); ffma2(acc2[13], x, wc.y);
            x = packf2(xb.w, xb.w);
            ffma2(acc1[14], x, w1.x); ffma2(acc1[15], x, w1.y);
            ffma2(acc2[14], x, wc.x); ffma2(acc2[15], x, wc.y);
        }

#pragma unroll
        for (int n = 0; n < 8; n++) {
            float4 v;
            unpackf2(acc1[2 * n], v.x, v.y);
            unpackf2(acc1[2 * n + 1], v.z, v.w);
            *(float4*)(Vs + (n0 + n) * 64 + c0) = v;
        }

        float4 bb = *(const float4*)(b2s + c0);
        float4 z[8];
#pragma unroll
        for (int n = 0; n < 8; n++) {
            unpackf2(acc2[2 * n], z[n].x, z[n].y);
            unpackf2(acc2[2 * n + 1], z[n].z, z[n].w);
            z[n].x += bb.x; z[n].y += bb.y; z[n].z += bb.z; z[n].w += bb.w;
            if (degS[n0 + n] == 0) {
                float s0c = 0.f, s1c = 0.f, s2c = 0.f, s3c = 0.f;
                for (int k = 0; k < 64; k++) {
                    float xv = Xk[k * PN + n0 + n];
                    s0c += xv * g_M2[k * 64 + c0 + 0];
                    s1c += xv * g_M2[k * 64 + c0 + 1];
                    s2c += xv * g_M2[k * 64 + c0 + 2];
                    s3c += xv * g_M2[k * 64 + c0 + 3];
                }
                z[n].x -= s0c; z[n].y -= s1c; z[n].z -= s2c; z[n].w -= s3c;
            }
        }
        __syncthreads();   // all Xk reads done; Vs complete

        float* Zb = Xk;    // reuse X space for Z (node-major, stride 64)
#pragma unroll
        for (int n = 0; n < 8; n++)
            *(float4*)(Zb + (n0 + n) * 64 + c0) = z[n];
        __syncthreads();   // Zb ready

        for (int n = warp; n < NN; n += 16) {
            int lo = offS[n], hi = offS[n + 1];
            float a0 = 0.f, a1 = 0.f;
            int e = lo;
            for (; e + 4 <= hi; e += 4) {
                int i0 = srcS[e], i1 = srcS[e + 1], i2 = srcS[e + 2], i3 = srcS[e + 3];
                a0 += Vs[i0 * 64 + lane]      + Vs[i1 * 64 + lane]
                    + Vs[i2 * 64 + lane]      + Vs[i3 * 64 + lane];
                a1 += Vs[i0 * 64 + 32 + lane] + Vs[i1 * 64 + 32 + lane]
                    + Vs[i2 * 64 + 32 + lane] + Vs[i3 * 64 + 32 + lane];
            }
            for (; e < hi; e++) {
                int i0 = srcS[e];
                a0 += Vs[i0 * 64 + lane];
                a1 += Vs[i0 * 64 + 32 + lane];
            }
            float degf = (float)(hi - lo);
            float dinv = 1.f / fmaxf(degf, 1.f);
            float sn0 = s0S[n], sn1 = s1S[n];
            float cp0 = sn0 * G0s[lane]      + sn1 * G1s[lane]      + degf * Gbs[lane];
            float cp1 = sn0 * G0s[32 + lane] + sn1 * G1s[32 + lane] + degf * Gbs[32 + lane];
            float* op = out + ((size_t)t * NN + n) * 64;
            op[lane]      = Zb[n * 64 + lane]      + (a0 + cp0) * dinv;
            op[32 + lane] = Zb[n * 64 + 32 + lane] + (a1 + cp1) * dinv;
        }
        __syncthreads();   // protect Xk/Vs before next graph
    }
}

// ---------------- launch ----------------
extern "C" void kernel_launch(void* const* d_in, const int* in_sizes, int n_in,
                              void* d_out, int out_size)
{
    const float* aqi  = (const float*)d_in[0];
    const int*   conn = (const int*)  d_in[1];
    const float* cw   = (const float*)d_in[2];
    const float* embW = (const float*)d_in[3];
    const float* embB = (const float*)d_in[4];
    const float* Wih  = (const float*)d_in[5];
    const float* Whh  = (const float*)d_in[6];
    const float* bih  = (const float*)d_in[7];
    const float* bhh  = (const float*)d_in[8];
    const float* W1   = (const float*)d_in[9];
    const float* b1   = (const float*)d_in[10];
    const float* W2   = (const float*)d_in[11];
    const float* b2   = (const float*)d_in[12];
    float* out = (float*)d_out;

    setup_all<<<68, 1024>>>(conn, cw, W1, b1, W2, Whh, Wih, embW, embB, bih, bhh);
    cudaFuncSetAttribute(lstm_kernel, cudaFuncAttributeMaxDynamicSharedMemorySize,
                         LSMEM_BYTES);
    lstm_kernel<<<BN / S_L, 128, LSMEM_BYTES>>>(aqi);
    cudaFuncSetAttribute(gnn_fused, cudaFuncAttributeMaxDynamicSharedMemorySize,
                         FUSE_SMEM_BYTES);
    gnn_fused<<<TT / 3, 512, FUSE_SMEM_BYTES>>>(b2, out);
}

// round 12
// speedup vs baseline: 1.5961x; 1.0147x over previous
#include <cuda_runtime.h>

#define BB 16
#define LL 24
#define NN 256
#define EE 4096
#define TT (BB*LL)      // 384 graphs
#define BN (BB*NN)      // 4096 LSTM samples
#define PN 268          // padded node stride for transposed X (GNN)
#define VST 1028        // cg-major V stride (floats; multiple of 4 -> float4-aligned)

// ---------------- packed f32x2 helpers ----------------
__device__ __forceinline__ unsigned long long packf2(float lo, float hi) {
    unsigned long long r;
    asm("mov.b64 %0,{%1,%2};" : "=l"(r) : "f"(lo), "f"(hi));
    return r;
}
__device__ __forceinline__ void unpackf2(unsigned long long v, float& lo, float& hi) {
    asm("mov.b64 {%0,%1},%2;" : "=f"(lo), "=f"(hi) : "l"(v));
}
__device__ __forceinline__ void ffma2(unsigned long long& d, unsigned long long a,
                                      unsigned long long b) {
    asm("fma.rn.f32x2 %0,%1,%2,%0;" : "+l"(d) : "l"(a), "l"(b));
}
__device__ __forceinline__ float tanha(float x) {
    float r; asm("tanh.approx.f32 %0,%1;" : "=f"(r) : "f"(x)); return r;
}
__device__ __forceinline__ float fsig(float x) { return 0.5f * tanha(0.5f * x) + 0.5f; }

// ---------------- device scratch ----------------
__device__ float g_Hout[TT * NN * 64];     // 25 MB
__device__ float g_WhhT[64 * 256];         // Whh transposed [k][r]
__device__ float g_Af[256], g_Bf[256];     // folded input weights/bias per gate row
__device__ float g_M1[4096];
__device__ float g_M2[4096];
__device__ float g_Wc[4096];
__device__ float g_G0[64], g_G1[64], g_Gb[64];
__device__ float g_s0v[NN], g_s1v[NN];
__device__ int   g_deg[NN];
__device__ int   g_off[NN + 1];
__device__ int   g_src[EE];

// ---------------- merged setup ----------------
// block 0: graph/CSR; blocks 1..65: GNN weight folds; 66: Whh transpose; 67: Af/Bf
__global__ void setup_all(const int* __restrict__ conn,
                          const float* __restrict__ city_w,
                          const float* __restrict__ W1,    // [130,64]
                          const float* __restrict__ b1,    // [64]
                          const float* __restrict__ W2,    // [128,64]
                          const float* __restrict__ Whh,   // [256,64]
                          const float* __restrict__ Wih,   // [256,16]
                          const float* __restrict__ embW,  // [16]
                          const float* __restrict__ embB,  // [16]
                          const float* __restrict__ bih,   // [256]
                          const float* __restrict__ bhh)   // [256]
{
    int t = threadIdx.x;
    if (blockIdx.x == 0) {
        __shared__ float s0[NN], s1[NN];
        __shared__ int degs[NN], cur[NN], scan[NN];

        if (t < NN) { s0[t] = 0.f; s1[t] = 0.f; degs[t] = 0; }
        __syncthreads();

        const int* row = conn;
        const int* col = conn + EE;
        // 4 edges per thread, vectorized
        int4   c4  = ((const int4*)col)[t];
        float4 w01 = ((const float4*)city_w)[2 * t];
        float4 w23 = ((const float4*)city_w)[2 * t + 1];
        atomicAdd(&degs[c4.x], 1); atomicAdd(&s0[c4.x], w01.x); atomicAdd(&s1[c4.x], w01.y);
        atomicAdd(&degs[c4.y], 1); atomicAdd(&s0[c4.y], w01.z); atomicAdd(&s1[c4.y], w01.w);
        atomicAdd(&degs[c4.z], 1); atomicAdd(&s0[c4.z], w23.x); atomicAdd(&s1[c4.z], w23.y);
        atomicAdd(&degs[c4.w], 1); atomicAdd(&s0[c4.w], w23.z); atomicAdd(&s1[c4.w], w23.w);
        __syncthreads();

        if (t < NN) scan[t] = degs[t];
        __syncthreads();
        for (int d = 1; d < NN; d <<= 1) {
            int v = (t < NN && t >= d) ? scan[t - d] : 0;
            __syncthreads();
            if (t < NN) scan[t] += v;
            __syncthreads();
        }
        if (t < NN) {
            int excl = scan[t] - degs[t];
            g_off[t] = excl;
            cur[t] = excl;
            g_deg[t] = degs[t];
            g_s0v[t] = s0[t];
            g_s1v[t] = s1[t];
            if (t == NN - 1) g_off[NN] = scan[NN - 1];
        }
        __syncthreads();
        {
            int4 r4 = ((const int4*)row)[t];
            int p;
            p = atomicAdd(&cur[c4.x], 1); g_src[p] = r4.x;
            p = atomicAdd(&cur[c4.y], 1); g_src[p] = r4.y;
            p = atomicAdd(&cur[c4.z], 1); g_src[p] = r4.z;
            p = atomicAdd(&cur[c4.w], 1); g_src[p] = r4.w;
        }
    } else if (blockIdx.x <= 65) {
        int k = blockIdx.x - 1;
        int c = t;
        const float* W2b = W2 + 4096;
        if (k < 64) {
            __shared__ float w1a[64], w1b[64];
            if (c < 64) { w1a[c] = W1[k * 64 + c]; w1b[c] = W1[4096 + k * 64 + c]; }
            __syncthreads();
            if (c < 64) {
                float p0 = 0.f, p1 = 0.f, p2 = 0.f, p3 = 0.f;
                float q0 = 0.f, q1 = 0.f, q2 = 0.f, q3 = 0.f;
#pragma unroll
                for (int j = 0; j < 64; j += 4) {
                    float v0 = W2b[(j + 0) * 64 + c];
                    float v1 = W2b[(j + 1) * 64 + c];
                    float v2 = W2b[(j + 2) * 64 + c];
                    float v3 = W2b[(j + 3) * 64 + c];
                    p0 += w1a[j + 0] * v0; q0 += w1b[j + 0] * v0;
                    p1 += w1a[j + 1] * v1; q1 += w1b[j + 1] * v1;
                    p2 += w1a[j + 2] * v2; q2 += w1b[j + 2] * v2;
                    p3 += w1a[j + 3] * v3; q3 += w1b[j + 3] * v3;
                }
                float a1 = (p0 + p1) + (p2 + p3);
                float a2 = (q0 + q1) + (q2 + q3);
                g_M1[k * 64 + c] = a1;
                g_M2[k * 64 + c] = a2;
                g_Wc[k * 64 + c] = W2[k * 64 + c] + a2;
            }
        } else if (c < 64) {
            float a0 = 0.f, a1 = 0.f, ab = 0.f;
#pragma unroll 8
            for (int j = 0; j < 64; j++) {
                float w2 = W2b[j * 64 + c];
                a0 += W1[128 * 64 + j] * w2;
                a1 += W1[129 * 64 + j] * w2;
                ab += b1[j] * w2;
            }
            g_G0[c] = a0; g_G1[c] = a1; g_Gb[c] = ab;
        }
    } else if (blockIdx.x == 66) {
        for (int idx = t; idx < 64 * 256; idx += 1024) {
            int k = idx >> 8, r = idx & 255;
            g_WhhT[idx] = Whh[r * 64 + k];
        }
    } else {
        if (t < 256) {
            float A = 0.f, B = 0.f;
#pragma unroll
            for (int j = 0; j < 16; j++) {
                float wi = Wih[t * 16 + j];
                A += wi * embW[j];
                B += wi * embB[j];
            }
            g_Af[t] = A;
            g_Bf[t] = B + bih[t] + bhh[t];
        }
    }
}

// ---------------- LSTM v2: smem-weight register-tiled GEMM (unchanged) ---------
#define S_L 16
#define HTS 36
#define GSS 260
#define LSMEM_FLOATS (16384 + 64*HTS + S_L*GSS + 256 + 256 + S_L*LL)
#define LSMEM_BYTES  (LSMEM_FLOATS * 4)

__global__ void __launch_bounds__(128)
lstm_kernel(const float* __restrict__ aqi)
{
    extern __shared__ __align__(16) float ls[];
    float* WT = ls;                    // [k][256]  64KB
    float* hT = ls + 16384;            // [k][HTS]
    float* gS = hT + 64 * HTS;         // [s][GSS]
    float* Af = gS + S_L * GSS;        // 256
    float* Bf = Af + 256;              // 256
    float* aS = Bf + 256;              // [s][LL]

    int tid = threadIdx.x;
    int m0 = blockIdx.x * S_L;
    int b = m0 >> 8, n0 = m0 & 255;

    {
        float4* d = (float4*)WT;
        const float4* s4 = (const float4*)g_WhhT;
        for (int i = tid; i < 4096; i += 128) d[i] = s4[i];
    }
    for (int i = tid; i < 64 * HTS; i += 128) hT[i] = 0.f;
    for (int i = tid; i < 256; i += 128) { Af[i] = g_Af[i]; Bf[i] = g_Bf[i]; }
    for (int i = tid; i < S_L * LL; i += 128) {
        int s = i / LL, l = i % LL;
        aS[i] = aqi[(b * LL + l) * NN + (n0 + s)];
    }
    __syncthreads();

    int sg = tid >> 6, cg = tid & 63;
    int s0 = sg * 8, c0 = cg * 4;
    int se = tid & 15, j0 = (tid >> 4) * 8;

    float c_reg[8];
#pragma unroll
    for (int i = 0; i < 8; i++) c_reg[i] = 0.f;
    float* hout = g_Hout + ((size_t)(b * LL) * NN + (n0 + se)) * 64 + j0;

    for (int l = 0; l < LL; l++) {
        unsigned long long acc[16];
#pragma unroll
        for (int i = 0; i < 16; i++) acc[i] = 0ull;

#pragma unroll 4
        for (int k = 0; k < 64; k++) {
            ulonglong2 hA = *(const ulonglong2*)(hT + k * HTS + s0);
            ulonglong2 hB = *(const ulonglong2*)(hT + k * HTS + s0 + 4);
            float4 w4 = *(const float4*)(WT + k * 256 + c0);
            unsigned long long w0 = packf2(w4.x, w4.x);
            unsigned long long w1 = packf2(w4.y, w4.y);
            unsigned long long w2 = packf2(w4.z, w4.z);
            unsigned long long w3 = packf2(w4.w, w4.w);
            ffma2(acc[0],  hA.x, w0); ffma2(acc[1],  hA.x, w1);
            ffma2(acc[2],  hA.x, w2); ffma2(acc[3],  hA.x, w3);
            ffma2(acc[4],  hA.y, w0); ffma2(acc[5],  hA.y, w1);
            ffma2(acc[6],  hA.y, w2); ffma2(acc[7],  hA.y, w3);
            ffma2(acc[8],  hB.x, w0); ffma2(acc[9],  hB.x, w1);
            ffma2(acc[10], hB.x, w2); ffma2(acc[11], hB.x, w3);
            ffma2(acc[12], hB.y, w0); ffma2(acc[13], hB.y, w1);
            ffma2(acc[14], hB.y, w2); ffma2(acc[15], hB.y, w3);
        }

        {
            float4 af = *(const float4*)(Af + c0);
            float4 bf = *(const float4*)(Bf + c0);
#pragma unroll
            for (int j = 0; j < 4; j++) {
                float4 glo, ghi;
                unpackf2(acc[4 * j + 0], glo.x, ghi.x);
                unpackf2(acc[4 * j + 1], glo.y, ghi.y);
                unpackf2(acc[4 * j + 2], glo.z, ghi.z);
                unpackf2(acc[4 * j + 3], glo.w, ghi.w);
                float alo = aS[(s0 + 2 * j) * LL + l];
                float ahi = aS[(s0 + 2 * j + 1) * LL + l];
                glo.x += alo * af.x + bf.x; glo.y += alo * af.y + bf.y;
                glo.z += alo * af.z + bf.z; glo.w += alo * af.w + bf.w;
                ghi.x += ahi * af.x + bf.x; ghi.y += ahi * af.y + bf.y;
                ghi.z += ahi * af.z + bf.z; ghi.w += ahi * af.w + bf.w;
                *(float4*)(gS + (s0 + 2 * j) * GSS + c0) = glo;
                *(float4*)(gS + (s0 + 2 * j + 1) * GSS + c0) = ghi;
            }
        }
        __syncthreads();

        {
            const float* gr = gS + se * GSS;
            float4 gi0 = *(const float4*)(gr + j0);
            float4 gi1 = *(const float4*)(gr + j0 + 4);
            float4 gf0 = *(const float4*)(gr + 64 + j0);
            float4 gf1 = *(const float4*)(gr + 64 + j0 + 4);
            float4 gg0 = *(const float4*)(gr + 128 + j0);
            float4 gg1 = *(const float4*)(gr + 128 + j0 + 4);
            float4 go0 = *(const float4*)(gr + 192 + j0);
            float4 go1 = *(const float4*)(gr + 192 + j0 + 4);

            float hv[8];
            float gi[8] = {gi0.x, gi0.y, gi0.z, gi0.w, gi1.x, gi1.y, gi1.z, gi1.w};
            float gf[8] = {gf0.x, gf0.y, gf0.z, gf0.w, gf1.x, gf1.y, gf1.z, gf1.w};
            float gg[8] = {gg0.x, gg0.y, gg0.z, gg0.w, gg1.x, gg1.y, gg1.z, gg1.w};
            float go[8] = {go0.x, go0.y, go0.z, go0.w, go1.x, go1.y, go1.z, go1.w};
#pragma unroll
            for (int i = 0; i < 8; i++) {
                float cn = fsig(gf[i]) * c_reg[i] + fsig(gi[i]) * tanha(gg[i]);
                c_reg[i] = cn;
                hv[i] = fsig(go[i]) * tanha(cn);
            }
#pragma unroll
            for (int i = 0; i < 8; i++)
                hT[(j0 + i) * HTS + se] = hv[i];
            float4 o0 = {hv[0], hv[1], hv[2], hv[3]};
            float4 o1 = {hv[4], hv[5], hv[6], hv[7]};
            *(float4*)(hout + (size_t)l * NN * 64) = o0;
            *(float4*)(hout + (size_t)l * NN * 64 + 4) = o1;
        }
        __syncthreads();
    }
}

// ---------------- fused GNN: aligned gather, Z in registers ----------------
#define FUSE_SMEM_FLOATS (64*PN + 16*VST + 4096 + 4096 + 64 + 192 + 512 + 4096 + 257 + 256)
#define FUSE_SMEM_BYTES  (FUSE_SMEM_FLOATS * 4)

__global__ void __launch_bounds__(512, 1)
gnn_fused(const float* __restrict__ b2, float* __restrict__ out)
{
    extern __shared__ __align__(16) float sm[];
    float* Xk  = sm;                       // 64*PN transposed X
    float* Vs  = Xk + 64 * PN;             // cg-major V: [cg][VST]
    float* W1s = Vs + 16 * VST;            // 4096
    float* Wcs = W1s + 4096;               // 4096
    float* b2s = Wcs + 4096;               // 64
    float* G0s = b2s + 64;                 // 64
    float* G1s = G0s + 64;                 // 64
    float* Gbs = G1s + 64;                 // 64
    float* s0S = Gbs + 64;                 // 256
    float* s1S = s0S + 256;                // 256
    int* srcS  = (int*)(s1S + 256);        // 4096
    int* offS  = srcS + EE;                // 257
    int* degS  = offS + NN + 1;            // 256

    int tid = threadIdx.x;
    for (int i = tid; i < 4096; i += 512) {
        W1s[i] = g_M1[i];
        Wcs[i] = g_Wc[i];
        srcS[i] = g_src[i];
    }
    if (tid < 64) {
        b2s[tid] = b2[tid];
        G0s[tid] = g_G0[tid]; G1s[tid] = g_G1[tid]; Gbs[tid] = g_Gb[tid];
    }
    if (tid < 256) { s0S[tid] = g_s0v[tid]; s1S[tid] = g_s1v[tid]; degS[tid] = g_deg[tid]; }
    if (tid < 257) offS[tid] = g_off[tid];

    int cg = tid & 15, ng = tid >> 4;
    int c0 = cg * 4, n0 = ng * 8;
    float* Vcg = Vs + cg * VST;

    for (int g = 0; g < 3; g++) {
        int t = blockIdx.x * 3 + g;
        const float* Xg = g_Hout + (size_t)t * NN * 64;
        for (int idx = tid; idx < NN * 64; idx += 512) {
            int n = idx >> 6, c = idx & 63;
            Xk[c * PN + n] = Xg[idx];
        }
        __syncthreads();   // X ready (also covers constants on g==0)

        unsigned long long acc1[16], acc2[16];
#pragma unroll
        for (int i = 0; i < 16; i++) { acc1[i] = 0ull; acc2[i] = 0ull; }

        // ---- fused mm1 (V = X@M1) + mm2 (Z = X@Wc) : X read once ----
#pragma unroll 4
        for (int k = 0; k < 64; k++) {
            float4 xa = *(const float4*)(Xk + k * PN + n0);
            float4 xb = *(const float4*)(Xk + k * PN + n0 + 4);
            ulonglong2 w1 = *(const ulonglong2*)(W1s + k * 64 + c0);
            ulonglong2 wc = *(const ulonglong2*)(Wcs + k * 64 + c0);
            unsigned long long x;
            x = packf2(xa.x, xa.x);
            ffma2(acc1[0],  x, w1.x); ffma2(acc1[1],  x, w1.y);
            ffma2(acc2[0],  x, wc.x); ffma2(acc2[1],  x, wc.y);
            x = packf2(xa.y, xa.y);
            ffma2(acc1[2],  x, w1.x); ffma2(acc1[3],  x, w1.y);
            ffma2(acc2[2],  x, wc.x); ffma2(acc2[3],  x, wc.y);
            x = packf2(xa.z, xa.z);
            ffma2(acc1[4],  x, w1.x); ffma2(acc1[5],  x, w1.y);
            ffma2(acc2[4],  x, wc.x); ffma2(acc2[5],  x, wc.y);
            x = packf2(xa.w, xa.w);
            ffma2(acc1[6],  x, w1.x); ffma2(acc1[7],  x, w1.y);
            ffma2(acc2[6],  x, wc.x); ffma2(acc2[7],  x, wc.y);
            x = packf2(xb.x, xb.x);
            ffma2(acc1[8],  x, w1.x); ffma2(acc1[9],  x, w1.y);
            ffma2(acc2[8],  x, wc.x); ffma2(acc2[9],  x, wc.y);
            x = packf2(xb.y, xb.y);
            ffma2(acc1[10], x, w1.x); ffma2(acc1[11], x, w1.y);
            ffma2(acc2[10], x, wc.x); ffma2(acc2[11], x, wc.y);
            x = packf2(xb.z, xb.z);
            ffma2(acc1[12], x, w1.x); ffma2(acc1[13], x, w1.y);
            ffma2(acc2[12], x, wc.x); ffma2(acc2[13], x, wc.y);
            x = packf2(xb.w, xb.w);
            ffma2(acc1[14], x, w1.x); ffma2(acc1[15], x, w1.y);
            ffma2(acc2[14], x, wc.x); ffma2(acc2[15], x, wc.y);
        }

        // V -> Vs (cg-major, conflict-free, float4-aligned)
#pragma unroll
        for (int n = 0; n < 8; n++) {
            float4 v;
            unpackf2(acc1[2 * n], v.x, v.y);
            unpackf2(acc1[2 * n + 1], v.z, v.w);
            *(float4*)(Vcg + (n0 + n) * 4) = v;
        }

        // Z = acc2 + b2 in registers (deg==0 rare path: subtract X@M2)
        float4 bb = *(const float4*)(b2s + c0);
        float4 z[8];
#pragma unroll
        for (int n = 0; n < 8; n++) {
            unpackf2(acc2[2 * n], z[n].x, z[n].y);
            unpackf2(acc2[2 * n + 1], z[n].z, z[n].w);
            z[n].x += bb.x; z[n].y += bb.y; z[n].z += bb.z; z[n].w += bb.w;
            if (degS[n0 + n] == 0) {
                float s0c = 0.f, s1c = 0.f, s2c = 0.f, s3c = 0.f;
                for (int k = 0; k < 64; k++) {
                    float xv = Xk[k * PN + n0 + n];
                    s0c += xv * g_M2[k * 64 + c0 + 0];
                    s1c += xv * g_M2[k * 64 + c0 + 1];
                    s2c += xv * g_M2[k * 64 + c0 + 2];
                    s3c += xv * g_M2[k * 64 + c0 + 3];
                }
                z[n].x -= s0c; z[n].y -= s1c; z[n].z -= s2c; z[n].w -= s3c;
            }
        }
        __syncthreads();   // V complete; Xk reads done

        // ---- gather + epilogue: same thread owns its 8 nodes x 4 channels ----
        float4 G0_4 = *(const float4*)(G0s + c0);
        float4 G1_4 = *(const float4*)(G1s + c0);
        float4 Gb_4 = *(const float4*)(Gbs + c0);
        float* og = out + (size_t)t * NN * 64;
#pragma unroll
        for (int n = 0; n < 8; n++) {
            int node = n0 + n;
            int lo = offS[node], hi = offS[node + 1];
            float4 a = {0.f, 0.f, 0.f, 0.f};
            float4 a2 = {0.f, 0.f, 0.f, 0.f};
            int e = lo;
            for (; e + 2 <= hi; e += 2) {
                int i0 = srcS[e], i1 = srcS[e + 1];
                float4 v0 = *(const float4*)(Vcg + i0 * 4);
                float4 v1 = *(const float4*)(Vcg + i1 * 4);
                a.x += v0.x; a.y += v0.y; a.z += v0.z; a.w += v0.w;
                a2.x += v1.x; a2.y += v1.y; a2.z += v1.z; a2.w += v1.w;
            }
            if (e < hi) {
                int i0 = srcS[e];
                float4 v0 = *(const float4*)(Vcg + i0 * 4);
                a.x += v0.x; a.y += v0.y; a.z += v0.z; a.w += v0.w;
            }
            a.x += a2.x; a.y += a2.y; a.z += a2.z; a.w += a2.w;

            float degf = (float)(hi - lo);
            float dinv = 1.f / fmaxf(degf, 1.f);
            float sn0 = s0S[node], sn1 = s1S[node];
            float4 o;
            o.x = z[n].x + (a.x + sn0 * G0_4.x + sn1 * G1_4.x + degf * Gb_4.x) * dinv;
            o.y = z[n].y + (a.y + sn0 * G0_4.y + sn1 * G1_4.y + degf * Gb_4.y) * dinv;
            o.z = z[n].z + (a.z + sn0 * G0_4.z + sn1 * G1_4.z + degf * Gb_4.z) * dinv;
            o.w = z[n].w + (a.w + sn0 * G0_4.w + sn1 * G1_4.w + degf * Gb_4.w) * dinv;
            *(float4*)(og + node * 64 + c0) = o;
        }
        __syncthreads();   // protect Xk/Vs before next graph
    }
}

// ---------------- launch ----------------
extern "C" void kernel_launch(void* const* d_in, const int* in_sizes, int n_in,
                              void* d_out, int out_size)
{
    const float* aqi  = (const float*)d_in[0];
    const int*   conn = (const int*)  d_in[1];
    const float* cw   = (const float*)d_in[2];
    const float* embW = (const float*)d_in[3];
    const float* embB = (const float*)d_in[4];
    const float* Wih  = (const float*)d_in[5];
    const float* Whh  = (const float*)d_in[6];
    const float* bih  = (const float*)d_in[7];
    const float* bhh  = (const float*)d_in[8];
    const float* W1   = (const float*)d_in[9];
    const float* b1   = (const float*)d_in[10];
    const float* W2   = (const float*)d_in[11];
    const float* b2   = (const float*)d_in[12];
    float* out = (float*)d_out;

    setup_all<<<68, 1024>>>(conn, cw, W1, b1, W2, Whh, Wih, embW, embB, bih, bhh);
    cudaFuncSetAttribute(lstm_kernel, cudaFuncAttributeMaxDynamicSharedMemorySize,
                         LSMEM_BYTES);
    lstm_kernel<<<BN / S_L, 128, LSMEM_BYTES>>>(aqi);
    cudaFuncSetAttribute(gnn_fused, cudaFuncAttributeMaxDynamicSharedMemorySize,
                         FUSE_SMEM_BYTES);
    gnn_fused<<<TT / 3, 512, FUSE_SMEM_BYTES>>>(b2, out);
}

// round 13
// speedup vs baseline: 1.6635x; 1.0422x over previous
#include <cuda_runtime.h>

#define BB 16
#define LL 24
#define NN 256
#define EE 4096
#define TT (BB*LL)      // 384 graphs
#define BN (BB*NN)      // 4096 LSTM samples
#define PN 268          // padded node stride for transposed X (GNN)
#define VST 1028        // cg-major V stride (floats; multiple of 4 -> float4-aligned)
#define NSETUP 17       // setup blocks prepended to the lstm launch

// ---------------- packed f32x2 helpers ----------------
__device__ __forceinline__ unsigned long long packf2(float lo, float hi) {
    unsigned long long r;
    asm("mov.b64 %0,{%1,%2};" : "=l"(r) : "f"(lo), "f"(hi));
    return r;
}
__device__ __forceinline__ void unpackf2(unsigned long long v, float& lo, float& hi) {
    asm("mov.b64 {%0,%1},%2;" : "=f"(lo), "=f"(hi) : "l"(v));
}
__device__ __forceinline__ void ffma2(unsigned long long& d, unsigned long long a,
                                      unsigned long long b) {
    asm("fma.rn.f32x2 %0,%1,%2,%0;" : "+l"(d) : "l"(a), "l"(b));
}
__device__ __forceinline__ float tanha(float x) {
    float r; asm("tanh.approx.f32 %0,%1;" : "=f"(r) : "f"(x)); return r;
}
__device__ __forceinline__ float fsig(float x) { return 0.5f * tanha(0.5f * x) + 0.5f; }

// ---------------- device scratch ----------------
__device__ float g_Hout[TT * NN * 64];     // 25 MB
__device__ float g_WhhT[64 * 256];         // Whh transposed [k][r]
__device__ float g_Af[256], g_Bf[256];     // folded input weights/bias per gate row
__device__ float g_M1[4096];
__device__ float g_M2[4096];
__device__ float g_Wc[4096];
__device__ float g_G0[64], g_G1[64], g_Gb[64];
__device__ float g_s0v[NN], g_s1v[NN];
__device__ int   g_deg[NN];
__device__ int   g_off[NN + 1];
__device__ int   g_src[EE];

// ---------------- tiny setup the LSTM depends on ----------------
__global__ void setup_lstm(const float* __restrict__ Whh,   // [256,64]
                           const float* __restrict__ Wih,   // [256,16]
                           const float* __restrict__ embW,  // [16]
                           const float* __restrict__ embB,  // [16]
                           const float* __restrict__ bih,   // [256]
                           const float* __restrict__ bhh)   // [256]
{
    int t = threadIdx.x;
    for (int idx = t; idx < 64 * 256; idx += 1024) {
        int k = idx >> 8, r = idx & 255;
        g_WhhT[idx] = Whh[r * 64 + k];
    }
    if (t < 256) {
        float A = 0.f, B = 0.f;
#pragma unroll
        for (int j = 0; j < 16; j++) {
            float wi = Wih[t * 16 + j];
            A += wi * embW[j];
            B += wi * embB[j];
        }
        g_Af[t] = A;
        g_Bf[t] = B + bih[t] + bhh[t];
    }
}

// ---------------- LSTM + GNN-setup unified kernel ----------------
// blocks 0..16: GNN setup (CSR + weight folds); blocks 17..272: LSTM.
#define S_L 16
#define HTS 36
#define GSS 260
#define LSMEM_FLOATS (16384 + 64*HTS + S_L*GSS + 256 + 256 + S_L*LL)
#define LSMEM_BYTES  (LSMEM_FLOATS * 4)

__global__ void __launch_bounds__(128)
lstm_setup_kernel(const float* __restrict__ aqi,
                  const int* __restrict__ conn,
                  const float* __restrict__ city_w,
                  const float* __restrict__ W1,   // [130,64]
                  const float* __restrict__ b1,   // [64]
                  const float* __restrict__ W2)   // [128,64]
{
    extern __shared__ __align__(16) float ls[];
    int tid = threadIdx.x;
    int bid = blockIdx.x;

    if (bid == 0) {
        // ---- CSR/graph + G0/G1/Gb fold ----
        float* s0 = ls;                  // 256
        float* s1 = ls + 256;            // 256
        int* degs = (int*)(ls + 512);    // 256
        int* cur  = degs + 256;          // 256
        int* scan = cur + 256;           // 256

        s0[tid] = 0.f; s0[tid + 128] = 0.f;
        s1[tid] = 0.f; s1[tid + 128] = 0.f;
        degs[tid] = 0; degs[tid + 128] = 0;
        __syncthreads();

        const int* row = conn;
        const int* col = conn + EE;
#pragma unroll 4
        for (int e = tid; e < EE; e += 128) {
            int c = col[e];
            atomicAdd(&degs[c], 1);
            atomicAdd(&s0[c], city_w[2 * e + 0]);
            atomicAdd(&s1[c], city_w[2 * e + 1]);
        }
        __syncthreads();

        // inclusive scan of 256 with 128 threads (2 elems each)
        scan[tid] = degs[tid]; scan[tid + 128] = degs[tid + 128];
        __syncthreads();
        for (int d = 1; d < 256; d <<= 1) {
            int v0 = (tid >= d) ? scan[tid - d] : 0;
            int v1 = (tid + 128 >= d) ? scan[tid + 128 - d] : 0;
            __syncthreads();
            scan[tid] += v0; scan[tid + 128] += v1;
            __syncthreads();
        }
#pragma unroll
        for (int u = 0; u < 2; u++) {
            int n = tid + u * 128;
            int excl = scan[n] - degs[n];
            g_off[n] = excl;
            cur[n] = excl;
            g_deg[n] = degs[n];
            g_s0v[n] = s0[n];
            g_s1v[n] = s1[n];
        }
        if (tid == 127) g_off[NN] = scan[255];
        __syncthreads();
#pragma unroll 4
        for (int e = tid; e < EE; e += 128) {
            int c = col[e];
            int p = atomicAdd(&cur[c], 1);
            g_src[p] = row[e];
        }

        // G0/G1/Gb fold (threads 0..63)
        if (tid < 64) {
            const float* W2b = W2 + 4096;
            float a0 = 0.f, a1 = 0.f, ab = 0.f;
#pragma unroll 8
            for (int j = 0; j < 64; j++) {
                float w2 = W2b[j * 64 + tid];
                a0 += W1[128 * 64 + j] * w2;
                a1 += W1[129 * 64 + j] * w2;
                ab += b1[j] * w2;
            }
            g_G0[tid] = a0; g_G1[tid] = a1; g_Gb[tid] = ab;
        }
        return;
    }
    if (bid < NSETUP) {
        // ---- weight folds: 4 k-rows per block ----
        int k0 = (bid - 1) * 4;
        int half = tid >> 6, c = tid & 63;
        const float* W2b = W2 + 4096;
#pragma unroll
        for (int it = 0; it < 2; it++) {
            int k = k0 + it * 2 + half;
            float p0 = 0.f, p1 = 0.f, p2 = 0.f, p3 = 0.f;
            float q0 = 0.f, q1 = 0.f, q2 = 0.f, q3 = 0.f;
            const float* w1a = W1 + k * 64;
            const float* w1b = W1 + 4096 + k * 64;
#pragma unroll
            for (int j = 0; j < 64; j += 4) {
                float v0 = W2b[(j + 0) * 64 + c];
                float v1 = W2b[(j + 1) * 64 + c];
                float v2 = W2b[(j + 2) * 64 + c];
                float v3 = W2b[(j + 3) * 64 + c];
                p0 += w1a[j + 0] * v0; q0 += w1b[j + 0] * v0;
                p1 += w1a[j + 1] * v1; q1 += w1b[j + 1] * v1;
                p2 += w1a[j + 2] * v2; q2 += w1b[j + 2] * v2;
                p3 += w1a[j + 3] * v3; q3 += w1b[j + 3] * v3;
            }
            float a1 = (p0 + p1) + (p2 + p3);
            float a2 = (q0 + q1) + (q2 + q3);
            g_M1[k * 64 + c] = a1;
            g_M2[k * 64 + c] = a2;
            g_Wc[k * 64 + c] = W2[k * 64 + c] + a2;
        }
        return;
    }

    // ---------------- LSTM body (identical to R12) ----------------
    float* WT = ls;                    // [k][256]  64KB
    float* hT = ls + 16384;            // [k][HTS]
    float* gS = hT + 64 * HTS;         // [s][GSS]
    float* Af = gS + S_L * GSS;        // 256
    float* Bf = Af + 256;              // 256
    float* aS = Bf + 256;              // [s][LL]

    int m0 = (bid - NSETUP) * S_L;
    int b = m0 >> 8, n0 = m0 & 255;

    {
        float4* d = (float4*)WT;
        const float4* s4 = (const float4*)g_WhhT;
        for (int i = tid; i < 4096; i += 128) d[i] = s4[i];
    }
    for (int i = tid; i < 64 * HTS; i += 128) hT[i] = 0.f;
    for (int i = tid; i < 256; i += 128) { Af[i] = g_Af[i]; Bf[i] = g_Bf[i]; }
    for (int i = tid; i < S_L * LL; i += 128) {
        int s = i / LL, l = i % LL;
        aS[i] = aqi[(b * LL + l) * NN + (n0 + s)];
    }
    __syncthreads();

    int sg = tid >> 6, cg = tid & 63;
    int s0 = sg * 8, c0 = cg * 4;
    int se = tid & 15, j0 = (tid >> 4) * 8;

    float c_reg[8];
#pragma unroll
    for (int i = 0; i < 8; i++) c_reg[i] = 0.f;
    float* hout = g_Hout + ((size_t)(b * LL) * NN + (n0 + se)) * 64 + j0;

    for (int l = 0; l < LL; l++) {
        unsigned long long acc[16];
#pragma unroll
        for (int i = 0; i < 16; i++) acc[i] = 0ull;

#pragma unroll 4
        for (int k = 0; k < 64; k++) {
            ulonglong2 hA = *(const ulonglong2*)(hT + k * HTS + s0);
            ulonglong2 hB = *(const ulonglong2*)(hT + k * HTS + s0 + 4);
            float4 w4 = *(const float4*)(WT + k * 256 + c0);
            unsigned long long w0 = packf2(w4.x, w4.x);
            unsigned long long w1 = packf2(w4.y, w4.y);
            unsigned long long w2 = packf2(w4.z, w4.z);
            unsigned long long w3 = packf2(w4.w, w4.w);
            ffma2(acc[0],  hA.x, w0); ffma2(acc[1],  hA.x, w1);
            ffma2(acc[2],  hA.x, w2); ffma2(acc[3],  hA.x, w3);
            ffma2(acc[4],  hA.y, w0); ffma2(acc[5],  hA.y, w1);
            ffma2(acc[6],  hA.y, w2); ffma2(acc[7],  hA.y, w3);
            ffma2(acc[8],  hB.x, w0); ffma2(acc[9],  hB.x, w1);
            ffma2(acc[10], hB.x, w2); ffma2(acc[11], hB.x, w3);
            ffma2(acc[12], hB.y, w0); ffma2(acc[13], hB.y, w1);
            ffma2(acc[14], hB.y, w2); ffma2(acc[15], hB.y, w3);
        }

        {
            float4 af = *(const float4*)(Af + c0);
            float4 bf = *(const float4*)(Bf + c0);
#pragma unroll
            for (int j = 0; j < 4; j++) {
                float4 glo, ghi;
                unpackf2(acc[4 * j + 0], glo.x, ghi.x);
                unpackf2(acc[4 * j + 1], glo.y, ghi.y);
                unpackf2(acc[4 * j + 2], glo.z, ghi.z);
                unpackf2(acc[4 * j + 3], glo.w, ghi.w);
                float alo = aS[(s0 + 2 * j) * LL + l];
                float ahi = aS[(s0 + 2 * j + 1) * LL + l];
                glo.x += alo * af.x + bf.x; glo.y += alo * af.y + bf.y;
                glo.z += alo * af.z + bf.z; glo.w += alo * af.w + bf.w;
                ghi.x += ahi * af.x + bf.x; ghi.y += ahi * af.y + bf.y;
                ghi.z += ahi * af.z + bf.z; ghi.w += ahi * af.w + bf.w;
                *(float4*)(gS + (s0 + 2 * j) * GSS + c0) = glo;
                *(float4*)(gS + (s0 + 2 * j + 1) * GSS + c0) = ghi;
            }
        }
        __syncthreads();

        {
            const float* gr = gS + se * GSS;
            float4 gi0 = *(const float4*)(gr + j0);
            float4 gi1 = *(const float4*)(gr + j0 + 4);
            float4 gf0 = *(const float4*)(gr + 64 + j0);
            float4 gf1 = *(const float4*)(gr + 64 + j0 + 4);
            float4 gg0 = *(const float4*)(gr + 128 + j0);
            float4 gg1 = *(const float4*)(gr + 128 + j0 + 4);
            float4 go0 = *(const float4*)(gr + 192 + j0);
            float4 go1 = *(const float4*)(gr + 192 + j0 + 4);

            float hv[8];
            float gi[8] = {gi0.x, gi0.y, gi0.z, gi0.w, gi1.x, gi1.y, gi1.z, gi1.w};
            float gf[8] = {gf0.x, gf0.y, gf0.z, gf0.w, gf1.x, gf1.y, gf1.z, gf1.w};
            float gg[8] = {gg0.x, gg0.y, gg0.z, gg0.w, gg1.x, gg1.y, gg1.z, gg1.w};
            float go[8] = {go0.x, go0.y, go0.z, go0.w, go1.x, go1.y, go1.z, go1.w};
#pragma unroll
            for (int i = 0; i < 8; i++) {
                float cn = fsig(gf[i]) * c_reg[i] + fsig(gi[i]) * tanha(gg[i]);
                c_reg[i] = cn;
                hv[i] = fsig(go[i]) * tanha(cn);
            }
#pragma unroll
            for (int i = 0; i < 8; i++)
                hT[(j0 + i) * HTS + se] = hv[i];
            float4 o0 = {hv[0], hv[1], hv[2], hv[3]};
            float4 o1 = {hv[4], hv[5], hv[6], hv[7]};
            *(float4*)(hout + (size_t)l * NN * 64) = o0;
            *(float4*)(hout + (size_t)l * NN * 64 + 4) = o1;
        }
        __syncthreads();
    }
}

// ---------------- fused GNN (identical to R12) ----------------
#define FUSE_SMEM_FLOATS (64*PN + 16*VST + 4096 + 4096 + 64 + 192 + 512 + 4096 + 257 + 256)
#define FUSE_SMEM_BYTES  (FUSE_SMEM_FLOATS * 4)

__global__ void __launch_bounds__(512, 1)
gnn_fused(const float* __restrict__ b2, float* __restrict__ out)
{
    extern __shared__ __align__(16) float sm[];
    float* Xk  = sm;                       // 64*PN transposed X
    float* Vs  = Xk + 64 * PN;             // cg-major V: [cg][VST]
    float* W1s = Vs + 16 * VST;            // 4096
    float* Wcs = W1s + 4096;               // 4096
    float* b2s = Wcs + 4096;               // 64
    float* G0s = b2s + 64;                 // 64
    float* G1s = G0s + 64;                 // 64
    float* Gbs = G1s + 64;                 // 64
    float* s0S = Gbs + 64;                 // 256
    float* s1S = s0S + 256;                // 256
    int* srcS  = (int*)(s1S + 256);        // 4096
    int* offS  = srcS + EE;                // 257
    int* degS  = offS + NN + 1;            // 256

    int tid = threadIdx.x;
    for (int i = tid; i < 4096; i += 512) {
        W1s[i] = g_M1[i];
        Wcs[i] = g_Wc[i];
        srcS[i] = g_src[i];
    }
    if (tid < 64) {
        b2s[tid] = b2[tid];
        G0s[tid] = g_G0[tid]; G1s[tid] = g_G1[tid]; Gbs[tid] = g_Gb[tid];
    }
    if (tid < 256) { s0S[tid] = g_s0v[tid]; s1S[tid] = g_s1v[tid]; degS[tid] = g_deg[tid]; }
    if (tid < 257) offS[tid] = g_off[tid];

    int cg = tid & 15, ng = tid >> 4;
    int c0 = cg * 4, n0 = ng * 8;
    float* Vcg = Vs + cg * VST;

    for (int g = 0; g < 3; g++) {
        int t = blockIdx.x * 3 + g;
        const float* Xg = g_Hout + (size_t)t * NN * 64;
        for (int idx = tid; idx < NN * 64; idx += 512) {
            int n = idx >> 6, c = idx & 63;
            Xk[c * PN + n] = Xg[idx];
        }
        __syncthreads();

        unsigned long long acc1[16], acc2[16];
#pragma unroll
        for (int i = 0; i < 16; i++) { acc1[i] = 0ull; acc2[i] = 0ull; }

#pragma unroll 4
        for (int k = 0; k < 64; k++) {
            float4 xa = *(const float4*)(Xk + k * PN + n0);
            float4 xb = *(const float4*)(Xk + k * PN + n0 + 4);
            ulonglong2 w1 = *(const ulonglong2*)(W1s + k * 64 + c0);
            ulonglong2 wc = *(const ulonglong2*)(Wcs + k * 64 + c0);
            unsigned long long x;
            x = packf2(xa.x, xa.x);
            ffma2(acc1[0],  x, w1.x); ffma2(acc1[1],  x, w1.y);
            ffma2(acc2[0],  x, wc.x); ffma2(acc2[1],  x, wc.y);
            x = packf2(xa.y, xa.y);
            ffma2(acc1[2],  x, w1.x); ffma2(acc1[3],  x, w1.y);
            ffma2(acc2[2],  x, wc.x); ffma2(acc2[3],  x, wc.y);
            x = packf2(xa.z, xa.z);
            ffma2(acc1[4],  x, w1.x); ffma2(acc1[5],  x, w1.y);
            ffma2(acc2[4],  x, wc.x); ffma2(acc2[5],  x, wc.y);
            x = packf2(xa.w, xa.w);
            ffma2(acc1[6],  x, w1.x); ffma2(acc1[7],  x, w1.y);
            ffma2(acc2[6],  x, wc.x); ffma2(acc2[7],  x, wc.y);
            x = packf2(xb.x, xb.x);
            ffma2(acc1[8],  x, w1.x); ffma2(acc1[9],  x, w1.y);
            ffma2(acc2[8],  x, wc.x); ffma2(acc2[9],  x, wc.y);
            x = packf2(xb.y, xb.y);
            ffma2(acc1[10], x, w1.x); ffma2(acc1[11], x, w1.y);
            ffma2(acc2[10], x, wc.x); ffma2(acc2[11], x, wc.y);
            x = packf2(xb.z, xb.z);
            ffma2(acc1[12], x, w1.x); ffma2(acc1[13], x, w1.y);
            ffma2(acc2[12], x, wc.x); ffma2(acc2[13], x, wc.y);
            x = packf2(xb.w, xb.w);
            ffma2(acc1[14], x, w1.x); ffma2(acc1[15], x, w1.y);
            ffma2(acc2[14], x, wc.x); ffma2(acc2[15], x, wc.y);
        }

#pragma unroll
        for (int n = 0; n < 8; n++) {
            float4 v;
            unpackf2(acc1[2 * n], v.x, v.y);
            unpackf2(acc1[2 * n + 1], v.z, v.w);
            *(float4*)(Vcg + (n0 + n) * 4) = v;
        }

        float4 bb = *(const float4*)(b2s + c0);
        float4 z[8];
#pragma unroll
        for (int n = 0; n < 8; n++) {
            unpackf2(acc2[2 * n], z[n].x, z[n].y);
            unpackf2(acc2[2 * n + 1], z[n].z, z[n].w);
            z[n].x += bb.x; z[n].y += bb.y; z[n].z += bb.z; z[n].w += bb.w;
            if (degS[n0 + n] == 0) {
                float s0c = 0.f, s1c = 0.f, s2c = 0.f, s3c = 0.f;
                for (int k = 0; k < 64; k++) {
                    float xv = Xk[k * PN + n0 + n];
                    s0c += xv * g_M2[k * 64 + c0 + 0];
                    s1c += xv * g_M2[k * 64 + c0 + 1];
                    s2c += xv * g_M2[k * 64 + c0 + 2];
                    s3c += xv * g_M2[k * 64 + c0 + 3];
                }
                z[n].x -= s0c; z[n].y -= s1c; z[n].z -= s2c; z[n].w -= s3c;
            }
        }
        __syncthreads();

        float4 G0_4 = *(const float4*)(G0s + c0);
        float4 G1_4 = *(const float4*)(G1s + c0);
        float4 Gb_4 = *(const float4*)(Gbs + c0);
        float* og = out + (size_t)t * NN * 64;
#pragma unroll
        for (int n = 0; n < 8; n++) {
            int node = n0 + n;
            int lo = offS[node], hi = offS[node + 1];
            float4 a = {0.f, 0.f, 0.f, 0.f};
            float4 a2 = {0.f, 0.f, 0.f, 0.f};
            int e = lo;
            for (; e + 2 <= hi; e += 2) {
                int i0 = srcS[e], i1 = srcS[e + 1];
                float4 v0 = *(const float4*)(Vcg + i0 * 4);
                float4 v1 = *(const float4*)(Vcg + i1 * 4);
                a.x += v0.x; a.y += v0.y; a.z += v0.z; a.w += v0.w;
                a2.x += v1.x; a2.y += v1.y; a2.z += v1.z; a2.w += v1.w;
            }
            if (e < hi) {
                int i0 = srcS[e];
                float4 v0 = *(const float4*)(Vcg + i0 * 4);
                a.x += v0.x; a.y += v0.y; a.z += v0.z; a.w += v0.w;
            }
            a.x += a2.x; a.y += a2.y; a.z += a2.z; a.w += a2.w;

            float degf = (float)(hi - lo);
            float dinv = 1.f / fmaxf(degf, 1.f);
            float sn0 = s0S[node], sn1 = s1S[node];
            float4 o;
            o.x = z[n].x + (a.x + sn0 * G0_4.x + sn1 * G1_4.x + degf * Gb_4.x) * dinv;
            o.y = z[n].y + (a.y + sn0 * G0_4.y + sn1 * G1_4.y + degf * Gb_4.y) * dinv;
            o.z = z[n].z + (a.z + sn0 * G0_4.z + sn1 * G1_4.z + degf * Gb_4.z) * dinv;
            o.w = z[n].w + (a.w + sn0 * G0_4.w + sn1 * G1_4.w + degf * Gb_4.w) * dinv;
            *(float4*)(og + node * 64 + c0) = o;
        }
        __syncthreads();
    }
}

// ---------------- launch ----------------
extern "C" void kernel_launch(void* const* d_in, const int* in_sizes, int n_in,
                              void* d_out, int out_size)
{
    const float* aqi  = (const float*)d_in[0];
    const int*   conn = (const int*)  d_in[1];
    const float* cw   = (const float*)d_in[2];
    const float* embW = (const float*)d_in[3];
    const float* embB = (const float*)d_in[4];
    const float* Wih  = (const float*)d_in[5];
    const float* Whh  = (const float*)d_in[6];
    const float* bih  = (const float*)d_in[7];
    const float* bhh  = (const float*)d_in[8];
    const float* W1   = (const float*)d_in[9];
    const float* b1   = (const float*)d_in[10];
    const float* W2   = (const float*)d_in[11];
    const float* b2   = (const float*)d_in[12];
    float* out = (float*)d_out;

    setup_lstm<<<1, 1024>>>(Whh, Wih, embW, embB, bih, bhh);
    cudaFuncSetAttribute(lstm_setup_kernel, cudaFuncAttributeMaxDynamicSharedMemorySize,
                         LSMEM_BYTES);
    lstm_setup_kernel<<<NSETUP + BN / S_L, 128, LSMEM_BYTES>>>(aqi, conn, cw, W1, b1, W2);
    cudaFuncSetAttribute(gnn_fused, cudaFuncAttributeMaxDynamicSharedMemorySize,
                         FUSE_SMEM_BYTES);
    gnn_fused<<<TT / 3, 512, FUSE_SMEM_BYTES>>>(b2, out);
}

// round 14
// speedup vs baseline: 1.7535x; 1.0541x over previous
#include <cuda_runtime.h>

#define BB 16
#define LL 24
#define NN 256
#define EE 4096
#define TT (BB*LL)      // 384 graphs
#define BN (BB*NN)      // 4096 LSTM samples
#define PN 268          // padded node stride for transposed X (GNN)
#define VST 1028        // cg-major V stride (floats; multiple of 4 -> float4-aligned)
#define NSETUP 17       // setup blocks prepended to the lstm launch

// ---------------- packed f32x2 helpers ----------------
__device__ __forceinline__ unsigned long long packf2(float lo, float hi) {
    unsigned long long r;
    asm("mov.b64 %0,{%1,%2};" : "=l"(r) : "f"(lo), "f"(hi));
    return r;
}
__device__ __forceinline__ void unpackf2(unsigned long long v, float& lo, float& hi) {
    asm("mov.b64 {%0,%1},%2;" : "=f"(lo), "=f"(hi) : "l"(v));
}
__device__ __forceinline__ void ffma2(unsigned long long& d, unsigned long long a,
                                      unsigned long long b) {
    asm("fma.rn.f32x2 %0,%1,%2,%0;" : "+l"(d) : "l"(a), "l"(b));
}
__device__ __forceinline__ float tanha(float x) {
    float r; asm("tanh.approx.f32 %0,%1;" : "=f"(r) : "f"(x)); return r;
}
__device__ __forceinline__ float fsig(float x) { return 0.5f * tanha(0.5f * x) + 0.5f; }

// ---------------- device scratch ----------------
__device__ float g_Hout[TT * NN * 64];     // 25 MB
__device__ float g_WhhT[64 * 256];         // Whh transposed [k][r]
__device__ float g_Af[256], g_Bf[256];     // folded input weights/bias per gate row
__device__ float g_M1[4096];
__device__ float g_M2[4096];
__device__ float g_Wc[4096];
__device__ float g_G0[64], g_G1[64], g_Gb[64];
__device__ float g_s0v[NN], g_s1v[NN];
__device__ int   g_deg[NN];
__device__ int   g_off[NN + 1];
__device__ int   g_src[EE];

// ---------------- tiny setup the LSTM depends on (tiled coalesced transpose) ----
__global__ void __launch_bounds__(256)
setup_lstm(const float* __restrict__ Whh,   // [256,64]
           const float* __restrict__ Wih,   // [256,16]
           const float* __restrict__ embW,  // [16]
           const float* __restrict__ embB,  // [16]
           const float* __restrict__ bih,   // [256]
           const float* __restrict__ bhh)   // [256]
{
    __shared__ float tile[32][65];
    int t = threadIdx.x;
    int bid = blockIdx.x;

    if (bid < 8) {
        int r0 = bid * 32;
        // coalesced load of 32x64 tile
#pragma unroll
        for (int u = 0; u < 8; u++) {
            int i = u * 256 + t;
            int r = i >> 6, k = i & 63;
            tile[r][k] = Whh[(r0 + r) * 64 + k];
        }
        __syncthreads();
        // coalesced transposed store: lane = r, warp covers k
        int rl = t & 31;
        int kb = t >> 5;   // 0..7
#pragma unroll
        for (int kk = 0; kk < 8; kk++) {
            int k = kb * 8 + kk;
            g_WhhT[k * 256 + r0 + rl] = tile[rl][k];
        }
    } else {
        // Af/Bf fold
        float A = 0.f, B = 0.f;
#pragma unroll
        for (int j = 0; j < 16; j++) {
            float wi = Wih[t * 16 + j];
            A += wi * embW[j];
            B += wi * embB[j];
        }
        g_Af[t] = A;
        g_Bf[t] = B + bih[t] + bhh[t];
    }
}

// ---------------- LSTM + GNN-setup unified kernel ----------------
// blocks 0..16: GNN setup (CSR + weight folds); blocks 17..272: LSTM.
#define S_L 16
#define HTS 36
#define GSS 260
#define LSMEM_FLOATS (16384 + 64*HTS + S_L*GSS + 256 + 256 + S_L*LL)
#define LSMEM_BYTES  (LSMEM_FLOATS * 4)

__global__ void __launch_bounds__(128)
lstm_setup_kernel(const float* __restrict__ aqi,
                  const int* __restrict__ conn,
                  const float* __restrict__ city_w,
                  const float* __restrict__ W1,   // [130,64]
                  const float* __restrict__ b1,   // [64]
                  const float* __restrict__ W2)   // [128,64]
{
    extern __shared__ __align__(16) float ls[];
    int tid = threadIdx.x;
    int bid = blockIdx.x;

    if (bid == 0) {
        // ---- CSR/graph + G0/G1/Gb fold ----
        float* s0 = ls;                  // 256
        float* s1 = ls + 256;            // 256
        int* degs = (int*)(ls + 512);    // 256
        int* cur  = degs + 256;          // 256
        int* scan = cur + 256;           // 256

        s0[tid] = 0.f; s0[tid + 128] = 0.f;
        s1[tid] = 0.f; s1[tid + 128] = 0.f;
        degs[tid] = 0; degs[tid + 128] = 0;
        __syncthreads();

        const int* row = conn;
        const int* col = conn + EE;
#pragma unroll 4
        for (int e = tid; e < EE; e += 128) {
            int c = col[e];
            atomicAdd(&degs[c], 1);
            atomicAdd(&s0[c], city_w[2 * e + 0]);
            atomicAdd(&s1[c], city_w[2 * e + 1]);
        }
        __syncthreads();

        // inclusive scan of 256 with 128 threads (2 elems each)
        scan[tid] = degs[tid]; scan[tid + 128] = degs[tid + 128];
        __syncthreads();
        for (int d = 1; d < 256; d <<= 1) {
            int v0 = (tid >= d) ? scan[tid - d] : 0;
            int v1 = (tid + 128 >= d) ? scan[tid + 128 - d] : 0;
            __syncthreads();
            scan[tid] += v0; scan[tid + 128] += v1;
            __syncthreads();
        }
#pragma unroll
        for (int u = 0; u < 2; u++) {
            int n = tid + u * 128;
            int excl = scan[n] - degs[n];
            g_off[n] = excl;
            cur[n] = excl;
            g_deg[n] = degs[n];
            g_s0v[n] = s0[n];
            g_s1v[n] = s1[n];
        }
        if (tid == 127) g_off[NN] = scan[255];
        __syncthreads();
#pragma unroll 4
        for (int e = tid; e < EE; e += 128) {
            int c = col[e];
            int p = atomicAdd(&cur[c], 1);
            g_src[p] = row[e];
        }

        // G0/G1/Gb fold (threads 0..63)
        if (tid < 64) {
            const float* W2b = W2 + 4096;
            float a0 = 0.f, a1 = 0.f, ab = 0.f;
#pragma unroll 8
            for (int j = 0; j < 64; j++) {
                float w2 = W2b[j * 64 + tid];
                a0 += W1[128 * 64 + j] * w2;
                a1 += W1[129 * 64 + j] * w2;
                ab += b1[j] * w2;
            }
            g_G0[tid] = a0; g_G1[tid] = a1; g_Gb[tid] = ab;
        }
        return;
    }
    if (bid < NSETUP) {
        // ---- weight folds: 4 k-rows per block ----
        int k0 = (bid - 1) * 4;
        int half = tid >> 6, c = tid & 63;
        const float* W2b = W2 + 4096;
#pragma unroll
        for (int it = 0; it < 2; it++) {
            int k = k0 + it * 2 + half;
            float p0 = 0.f, p1 = 0.f, p2 = 0.f, p3 = 0.f;
            float q0 = 0.f, q1 = 0.f, q2 = 0.f, q3 = 0.f;
            const float* w1a = W1 + k * 64;
            const float* w1b = W1 + 4096 + k * 64;
#pragma unroll
            for (int j = 0; j < 64; j += 4) {
                float v0 = W2b[(j + 0) * 64 + c];
                float v1 = W2b[(j + 1) * 64 + c];
                float v2 = W2b[(j + 2) * 64 + c];
                float v3 = W2b[(j + 3) * 64 + c];
                p0 += w1a[j + 0] * v0; q0 += w1b[j + 0] * v0;
                p1 += w1a[j + 1] * v1; q1 += w1b[j + 1] * v1;
                p2 += w1a[j + 2] * v2; q2 += w1b[j + 2] * v2;
                p3 += w1a[j + 3] * v3; q3 += w1b[j + 3] * v3;
            }
            float a1 = (p0 + p1) + (p2 + p3);
            float a2 = (q0 + q1) + (q2 + q3);
            g_M1[k * 64 + c] = a1;
            g_M2[k * 64 + c] = a2;
            g_Wc[k * 64 + c] = W2[k * 64 + c] + a2;
        }
        return;
    }

    // ---------------- LSTM body ----------------
    float* WT = ls;                    // [k][256]  64KB
    float* hT = ls + 16384;            // [k][HTS]
    float* gS = hT + 64 * HTS;         // [s][GSS]
    float* Af = gS + S_L * GSS;        // 256
    float* Bf = Af + 256;              // 256
    float* aS = Bf + 256;              // [s][LL]

    int m0 = (bid - NSETUP) * S_L;
    int b = m0 >> 8, n0 = m0 & 255;

    {
        float4* d = (float4*)WT;
        const float4* s4 = (const float4*)g_WhhT;
        for (int i = tid; i < 4096; i += 128) d[i] = s4[i];
    }
    for (int i = tid; i < 64 * HTS; i += 128) hT[i] = 0.f;
    for (int i = tid; i < 256; i += 128) { Af[i] = g_Af[i]; Bf[i] = g_Bf[i]; }
    for (int i = tid; i < S_L * LL; i += 128) {
        int s = i / LL, l = i % LL;
        aS[i] = aqi[(b * LL + l) * NN + (n0 + s)];
    }
    __syncthreads();

    int sg = tid >> 6, cg = tid & 63;
    int s0 = sg * 8, c0 = cg * 4;
    int se = tid & 15, j0 = (tid >> 4) * 8;

    float c_reg[8];
#pragma unroll
    for (int i = 0; i < 8; i++) c_reg[i] = 0.f;
    float* hout = g_Hout + ((size_t)(b * LL) * NN + (n0 + se)) * 64 + j0;

    for (int l = 0; l < LL; l++) {
        unsigned long long acc[16];
#pragma unroll
        for (int i = 0; i < 16; i++) acc[i] = 0ull;

#pragma unroll 4
        for (int k = 0; k < 64; k++) {
            ulonglong2 hA = *(const ulonglong2*)(hT + k * HTS + s0);
            ulonglong2 hB = *(const ulonglong2*)(hT + k * HTS + s0 + 4);
            float4 w4 = *(const float4*)(WT + k * 256 + c0);
            unsigned long long w0 = packf2(w4.x, w4.x);
            unsigned long long w1 = packf2(w4.y, w4.y);
            unsigned long long w2 = packf2(w4.z, w4.z);
            unsigned long long w3 = packf2(w4.w, w4.w);
            ffma2(acc[0],  hA.x, w0); ffma2(acc[1],  hA.x, w1);
            ffma2(acc[2],  hA.x, w2); ffma2(acc[3],  hA.x, w3);
            ffma2(acc[4],  hA.y, w0); ffma2(acc[5],  hA.y, w1);
            ffma2(acc[6],  hA.y, w2); ffma2(acc[7],  hA.y, w3);
            ffma2(acc[8],  hB.x, w0); ffma2(acc[9],  hB.x, w1);
            ffma2(acc[10], hB.x, w2); ffma2(acc[11], hB.x, w3);
            ffma2(acc[12], hB.y, w0); ffma2(acc[13], hB.y, w1);
            ffma2(acc[14], hB.y, w2); ffma2(acc[15], hB.y, w3);
        }

        {
            float4 af = *(const float4*)(Af + c0);
            float4 bf = *(const float4*)(Bf + c0);
#pragma unroll
            for (int j = 0; j < 4; j++) {
                float4 glo, ghi;
                unpackf2(acc[4 * j + 0], glo.x, ghi.x);
                unpackf2(acc[4 * j + 1], glo.y, ghi.y);
                unpackf2(acc[4 * j + 2], glo.z, ghi.z);
                unpackf2(acc[4 * j + 3], glo.w, ghi.w);
                float alo = aS[(s0 + 2 * j) * LL + l];
                float ahi = aS[(s0 + 2 * j + 1) * LL + l];
                glo.x += alo * af.x + bf.x; glo.y += alo * af.y + bf.y;
                glo.z += alo * af.z + bf.z; glo.w += alo * af.w + bf.w;
                ghi.x += ahi * af.x + bf.x; ghi.y += ahi * af.y + bf.y;
                ghi.z += ahi * af.z + bf.z; ghi.w += ahi * af.w + bf.w;
                *(float4*)(gS + (s0 + 2 * j) * GSS + c0) = glo;
                *(float4*)(gS + (s0 + 2 * j + 1) * GSS + c0) = ghi;
            }
        }
        __syncthreads();

        {
            const float* gr = gS + se * GSS;
            float4 gi0 = *(const float4*)(gr + j0);
            float4 gi1 = *(const float4*)(gr + j0 + 4);
            float4 gf0 = *(const float4*)(gr + 64 + j0);
            float4 gf1 = *(const float4*)(gr + 64 + j0 + 4);
            float4 gg0 = *(const float4*)(gr + 128 + j0);
            float4 gg1 = *(const float4*)(gr + 128 + j0 + 4);
            float4 go0 = *(const float4*)(gr + 192 + j0);
            float4 go1 = *(const float4*)(gr + 192 + j0 + 4);

            float hv[8];
            float gi[8] = {gi0.x, gi0.y, gi0.z, gi0.w, gi1.x, gi1.y, gi1.z, gi1.w};
            float gf[8] = {gf0.x, gf0.y, gf0.z, gf0.w, gf1.x, gf1.y, gf1.z, gf1.w};
            float gg[8] = {gg0.x, gg0.y, gg0.z, gg0.w, gg1.x, gg1.y, gg1.z, gg1.w};
            float go[8] = {go0.x, go0.y, go0.z, go0.w, go1.x, go1.y, go1.z, go1.w};
#pragma unroll
            for (int i = 0; i < 8; i++) {
                float cn = fsig(gf[i]) * c_reg[i] + fsig(gi[i]) * tanha(gg[i]);
                c_reg[i] = cn;
                hv[i] = fsig(go[i]) * tanha(cn);
            }
#pragma unroll
            for (int i = 0; i < 8; i++)
                hT[(j0 + i) * HTS + se] = hv[i];
            float4 o0 = {hv[0], hv[1], hv[2], hv[3]};
            float4 o1 = {hv[4], hv[5], hv[6], hv[7]};
            *(float4*)(hout + (size_t)l * NN * 64) = o0;
            *(float4*)(hout + (size_t)l * NN * 64 + 4) = o1;
        }
        __syncthreads();
    }
}

// ---------------- fused GNN (identical to R12/R13) ----------------
#define FUSE_SMEM_FLOATS (64*PN + 16*VST + 4096 + 4096 + 64 + 192 + 512 + 4096 + 257 + 256)
#define FUSE_SMEM_BYTES  (FUSE_SMEM_FLOATS * 4)

__global__ void __launch_bounds__(512, 1)
gnn_fused(const float* __restrict__ b2, float* __restrict__ out)
{
    extern __shared__ __align__(16) float sm[];
    float* Xk  = sm;                       // 64*PN transposed X
    float* Vs  = Xk + 64 * PN;             // cg-major V: [cg][VST]
    float* W1s = Vs + 16 * VST;            // 4096
    float* Wcs = W1s + 4096;               // 4096
    float* b2s = Wcs + 4096;               // 64
    float* G0s = b2s + 64;                 // 64
    float* G1s = G0s + 64;                 // 64
    float* Gbs = G1s + 64;                 // 64
    float* s0S = Gbs + 64;                 // 256
    float* s1S = s0S + 256;                // 256
    int* srcS  = (int*)(s1S + 256);        // 4096
    int* offS  = srcS + EE;                // 257
    int* degS  = offS + NN + 1;            // 256

    int tid = threadIdx.x;
    for (int i = tid; i < 4096; i += 512) {
        W1s[i] = g_M1[i];
        Wcs[i] = g_Wc[i];
        srcS[i] = g_src[i];
    }
    if (tid < 64) {
        b2s[tid] = b2[tid];
        G0s[tid] = g_G0[tid]; G1s[tid] = g_G1[tid]; Gbs[tid] = g_Gb[tid];
    }
    if (tid < 256) { s0S[tid] = g_s0v[tid]; s1S[tid] = g_s1v[tid]; degS[tid] = g_deg[tid]; }
    if (tid < 257) offS[tid] = g_off[tid];

    int cg = tid & 15, ng = tid >> 4;
    int c0 = cg * 4, n0 = ng * 8;
    float* Vcg = Vs + cg * VST;

    for (int g = 0; g < 3; g++) {
        int t = blockIdx.x * 3 + g;
        const float* Xg = g_Hout + (size_t)t * NN * 64;
        for (int idx = tid; idx < NN * 64; idx += 512) {
            int n = idx >> 6, c = idx & 63;
            Xk[c * PN + n] = Xg[idx];
        }
        __syncthreads();

        unsigned long long acc1[16], acc2[16];
#pragma unroll
        for (int i = 0; i < 16; i++) { acc1[i] = 0ull; acc2[i] = 0ull; }

#pragma unroll 4
        for (int k = 0; k < 64; k++) {
            float4 xa = *(const float4*)(Xk + k * PN + n0);
            float4 xb = *(const float4*)(Xk + k * PN + n0 + 4);
            ulonglong2 w1 = *(const ulonglong2*)(W1s + k * 64 + c0);
            ulonglong2 wc = *(const ulonglong2*)(Wcs + k * 64 + c0);
            unsigned long long x;
            x = packf2(xa.x, xa.x);
            ffma2(acc1[0],  x, w1.x); ffma2(acc1[1],  x, w1.y);
            ffma2(acc2[0],  x, wc.x); ffma2(acc2[1],  x, wc.y);
            x = packf2(xa.y, xa.y);
            ffma2(acc1[2],  x, w1.x); ffma2(acc1[3],  x, w1.y);
            ffma2(acc2[2],  x, wc.x); ffma2(acc2[3],  x, wc.y);
            x = packf2(xa.z, xa.z);
            ffma2(acc1[4],  x, w1.x); ffma2(acc1[5],  x, w1.y);
            ffma2(acc2[4],  x, wc.x); ffma2(acc2[5],  x, wc.y);
            x = packf2(xa.w, xa.w);
            ffma2(acc1[6],  x, w1.x); ffma2(acc1[7],  x, w1.y);
            ffma2(acc2[6],  x, wc.x); ffma2(acc2[7],  x, wc.y);
            x = packf2(xb.x, xb.x);
            ffma2(acc1[8],  x, w1.x); ffma2(acc1[9],  x, w1.y);
            ffma2(acc2[8],  x, wc.x); ffma2(acc2[9],  x, wc.y);
            x = packf2(xb.y, xb.y);
            ffma2(acc1[10], x, w1.x); ffma2(acc1[11], x, w1.y);
            ffma2(acc2[10], x, wc.x); ffma2(acc2[11], x, wc.y);
            x = packf2(xb.z, xb.z);
            ffma2(acc1[12], x, w1.x); ffma2(acc1[13], x, w1.y);
            ffma2(acc2[12], x, wc.x); ffma2(acc2[13], x, wc.y);
            x = packf2(xb.w, xb.w);
            ffma2(acc1[14], x, w1.x); ffma2(acc1[15], x, w1.y);
            ffma2(acc2[14], x, wc.x); ffma2(acc2[15], x, wc.y);
        }

#pragma unroll
        for (int n = 0; n < 8; n++) {
            float4 v;
            unpackf2(acc1[2 * n], v.x, v.y);
            unpackf2(acc1[2 * n + 1], v.z, v.w);
            *(float4*)(Vcg + (n0 + n) * 4) = v;
        }

        float4 bb = *(const float4*)(b2s + c0);
        float4 z[8];
#pragma unroll
        for (int n = 0; n < 8; n++) {
            unpackf2(acc2[2 * n], z[n].x, z[n].y);
            unpackf2(acc2[2 * n + 1], z[n].z, z[n].w);
            z[n].x += bb.x; z[n].y += bb.y; z[n].z += bb.z; z[n].w += bb.w;
            if (degS[n0 + n] == 0) {
                float s0c = 0.f, s1c = 0.f, s2c = 0.f, s3c = 0.f;
                for (int k = 0; k < 64; k++) {
                    float xv = Xk[k * PN + n0 + n];
                    s0c += xv * g_M2[k * 64 + c0 + 0];
                    s1c += xv * g_M2[k * 64 + c0 + 1];
                    s2c += xv * g_M2[k * 64 + c0 + 2];
                    s3c += xv * g_M2[k * 64 + c0 + 3];
                }
                z[n].x -= s0c; z[n].y -= s1c; z[n].z -= s2c; z[n].w -= s3c;
            }
        }
        __syncthreads();

        float4 G0_4 = *(const float4*)(G0s + c0);
        float4 G1_4 = *(const float4*)(G1s + c0);
        float4 Gb_4 = *(const float4*)(Gbs + c0);
        float* og = out + (size_t)t * NN * 64;
#pragma unroll
        for (int n = 0; n < 8; n++) {
            int node = n0 + n;
            int lo = offS[node], hi = offS[node + 1];
            float4 a = {0.f, 0.f, 0.f, 0.f};
            float4 a2 = {0.f, 0.f, 0.f, 0.f};
            int e = lo;
            for (; e + 2 <= hi; e += 2) {
                int i0 = srcS[e], i1 = srcS[e + 1];
                float4 v0 = *(const float4*)(Vcg + i0 * 4);
                float4 v1 = *(const float4*)(Vcg + i1 * 4);
                a.x += v0.x; a.y += v0.y; a.z += v0.z; a.w += v0.w;
                a2.x += v1.x; a2.y += v1.y; a2.z += v1.z; a2.w += v1.w;
            }
            if (e < hi) {
                int i0 = srcS[e];
                float4 v0 = *(const float4*)(Vcg + i0 * 4);
                a.x += v0.x; a.y += v0.y; a.z += v0.z; a.w += v0.w;
            }
            a.x += a2.x; a.y += a2.y; a.z += a2.z; a.w += a2.w;

            float degf = (float)(hi - lo);
            float dinv = 1.f / fmaxf(degf, 1.f);
            float sn0 = s0S[node], sn1 = s1S[node];
            float4 o;
            o.x = z[n].x + (a.x + sn0 * G0_4.x + sn1 * G1_4.x + degf * Gb_4.x) * dinv;
            o.y = z[n].y + (a.y + sn0 * G0_4.y + sn1 * G1_4.y + degf * Gb_4.y) * dinv;
            o.z = z[n].z + (a.z + sn0 * G0_4.z + sn1 * G1_4.z + degf * Gb_4.z) * dinv;
            o.w = z[n].w + (a.w + sn0 * G0_4.w + sn1 * G1_4.w + degf * Gb_4.w) * dinv;
            *(float4*)(og + node * 64 + c0) = o;
        }
        __syncthreads();
    }
}

// ---------------- launch ----------------
extern "C" void kernel_launch(void* const* d_in, const int* in_sizes, int n_in,
                              void* d_out, int out_size)
{
    const float* aqi  = (const float*)d_in[0];
    const int*   conn = (const int*)  d_in[1];
    const float* cw   = (const float*)d_in[2];
    const float* embW = (const float*)d_in[3];
    const float* embB = (const float*)d_in[4];
    const float* Wih  = (const float*)d_in[5];
    const float* Whh  = (const float*)d_in[6];
    const float* bih  = (const float*)d_in[7];
    const float* bhh  = (const float*)d_in[8];
    const float* W1   = (const float*)d_in[9];
    const float* b1   = (const float*)d_in[10];
    const float* W2   = (const float*)d_in[11];
    const float* b2   = (const float*)d_in[12];
    float* out = (float*)d_out;

    setup_lstm<<<9, 256>>>(Whh, Wih, embW, embB, bih, bhh);
    cudaFuncSetAttribute(lstm_setup_kernel, cudaFuncAttributeMaxDynamicSharedMemorySize,
                         LSMEM_BYTES);
    lstm_setup_kernel<<<NSETUP + BN / S_L, 128, LSMEM_BYTES>>>(aqi, conn, cw, W1, b1, W2);
    cudaFuncSetAttribute(gnn_fused, cudaFuncAttributeMaxDynamicSharedMemorySize,
                         FUSE_SMEM_BYTES);
    gnn_fused<<<TT / 3, 512, FUSE_SMEM_BYTES>>>(b2, out);
}